// round 5
// baseline (speedup 1.0000x reference)
#include <cuda_runtime.h>
#include <math.h>

// Problem dims
#define CH   768
#define H_   180
#define W_   360
#define WK   91           // kept W modes (rfft bins 0..90; 91..180 provably zero)
#define NB   8
#define BS   96
#define S_   (H_ * WK)    // 16380 spectral points per channel
#define ORTHO 0.003928371006591931f   // 1/sqrt(180*360)
#define LAM  0.01f

// Scratch ping-pong spectral buffers, layout: [c][h*WK + w] as float2
__device__ float2 g_S1[(size_t)CH * S_];
__device__ float2 g_S2[(size_t)CH * S_];

// Precomputed twiddle tables
__device__ float2 g_twWf[W_];   // e^{-2pi i n/360}
__device__ float2 g_twWb[W_];   // e^{+2pi i n/360}
__device__ float2 g_twHf[H_];   // e^{-2pi i n/180}
__device__ float2 g_twHb[H_];   // e^{+2pi i n/180}

__device__ __forceinline__ float2 cmul(float2 a, float2 b) {
    return make_float2(fmaf(a.x, b.x, -a.y * b.y),
                       fmaf(a.x, b.y,  a.y * b.x));
}

__global__ void k_init_tw() {
    int n = threadIdx.x;
    if (n < W_) {
        float s, c;
        sincospif((float)n / 180.0f, &s, &c);   // 2*pi*n/360
        g_twWf[n] = make_float2(c, -s);
        g_twWb[n] = make_float2(c,  s);
    }
    if (n < H_) {
        float s, c;
        sincospif((float)n / 90.0f, &s, &c);    // 2*pi*n/180
        g_twHf[n] = make_float2(c, -s);
        g_twHb[n] = make_float2(c,  s);
    }
}

// ---------------------------------------------------------------------------
// Kernel 1: forward DFT along W (real 360 -> bins 0..90), folded n<->360-n.
// X_w = x0 + (-1)^w x180 + sum_{n=1}^{179} [ p[n]*cos - i*m[n]*sin ](theta*w*n)
// One block per (c,h) row; threads 0..90 each produce one bin.
// ---------------------------------------------------------------------------
__global__ __launch_bounds__(128)
void k_fwd_w(const float* __restrict__ x) {
    __shared__ float  xr[W_];
    __shared__ float  p[H_];
    __shared__ float  m[H_];
    __shared__ float2 tw[W_];
    int row = blockIdx.x;                    // c*H + h
    const float* xp = x + (size_t)row * W_;
    for (int n = threadIdx.x; n < W_; n += 128) {
        xr[n] = xp[n];
        tw[n] = g_twWf[n];
    }
    __syncthreads();
    for (int n = threadIdx.x + 1; n < H_; n += 128) {
        p[n] = xr[n] + xr[W_ - n];
        m[n] = xr[n] - xr[W_ - n];
    }
    __syncthreads();
    int w = threadIdx.x;
    if (w < WK) {
        float re = xr[0] + ((w & 1) ? -xr[H_] : xr[H_]);
        float im = 0.f;
        int idx = w;                         // w*1 mod 360
        #pragma unroll 4
        for (int n = 1; n < H_; n++) {
            float2 e = tw[idx];              // (cos, -sin)
            re = fmaf(p[n], e.x, re);
            im = fmaf(m[n], e.y, im);        // accumulates -sum(m*sin)
            idx += w; if (idx >= W_) idx -= W_;
        }
        g_S1[(size_t)row * WK + w] = make_float2(re * ORTHO, im * ORTHO);
    }
}

// ---------------------------------------------------------------------------
// Kernels 2/5: 180-pt complex DFT along H, two-level DIT (radix-4 sharing).
// Thread computes PP/PQ/QP/QQ (45-term sums over h = 4r + {0,2,1,3}) at k,
// then butterflies to outputs k, k+45, k+90, k+135.
// ---------------------------------------------------------------------------
#define WT 13
template <int SGN>
__global__ __launch_bounds__(256)
void k_fft_h(const float2* __restrict__ in, float2* __restrict__ out) {
    __shared__ float2 tile[H_ * WT];
    __shared__ float2 tw[H_];
    int c  = blockIdx.y;
    int w0 = blockIdx.x * WT;
    const float2* base = in + (size_t)c * S_;
    for (int i = threadIdx.x; i < H_ * WT; i += 256) {
        int h = i / WT, wl = i % WT;
        tile[i] = base[(size_t)h * WK + w0 + wl];
    }
    const float2* gt = (SGN < 0) ? g_twHf : g_twHb;
    for (int n = threadIdx.x; n < H_; n += 256) tw[n] = gt[n];
    __syncthreads();
    float2* ob = out + (size_t)c * S_;
    for (int it = threadIdx.x; it < 45 * WT; it += 256) {
        int k  = it / WT, wl = it % WT;
        int s4 = (4 * k) % H_;
        float2 PP = make_float2(0.f, 0.f), PQ = PP, QP = PP, QQ = PP;
        int idx = 0;
        #pragma unroll 5
        for (int r = 0; r < 45; r++) {
            float2 e  = tw[idx];             // W^{4rk}
            float2 z0 = tile[(4 * r + 0) * WT + wl];
            float2 z1 = tile[(4 * r + 1) * WT + wl];
            float2 z2 = tile[(4 * r + 2) * WT + wl];
            float2 z3 = tile[(4 * r + 3) * WT + wl];
            PP.x = fmaf(z0.x, e.x, fmaf(-z0.y, e.y, PP.x));
            PP.y = fmaf(z0.x, e.y, fmaf( z0.y, e.x, PP.y));
            QP.x = fmaf(z1.x, e.x, fmaf(-z1.y, e.y, QP.x));
            QP.y = fmaf(z1.x, e.y, fmaf( z1.y, e.x, QP.y));
            PQ.x = fmaf(z2.x, e.x, fmaf(-z2.y, e.y, PQ.x));
            PQ.y = fmaf(z2.x, e.y, fmaf( z2.y, e.x, PQ.y));
            QQ.x = fmaf(z3.x, e.x, fmaf(-z3.y, e.y, QQ.x));
            QQ.y = fmaf(z3.x, e.y, fmaf( z3.y, e.x, QQ.y));
            idx += s4; if (idx >= H_) idx -= H_;
        }
        float2 w1t = tw[k];                  // W^k
        float2 w2t = tw[2 * k];              // W^{2k}  (2k <= 88)
        float2 t2  = cmul(w2t, PQ);
        float2 t2q = cmul(w2t, QQ);
        float2 Pp = make_float2(PP.x + t2.x,  PP.y + t2.y);
        float2 Pm = make_float2(PP.x - t2.x,  PP.y - t2.y);
        float2 Qp = make_float2(QP.x + t2q.x, QP.y + t2q.y);
        float2 Qm = make_float2(QP.x - t2q.x, QP.y - t2q.y);
        float2 up = cmul(w1t, Qp);
        float2 um = cmul(w1t, Qm);
        float2 iu = make_float2((float)(-SGN) * um.y, (float)SGN * um.x);
        size_t o0 = (size_t)k * WK + w0 + wl;
        ob[o0           ] = make_float2(Pp.x + up.x, Pp.y + up.y);
        ob[o0 +  45 * WK] = make_float2(Pm.x + iu.x, Pm.y + iu.y);
        ob[o0 +  90 * WK] = make_float2(Pp.x - up.x, Pp.y - up.y);
        ob[o0 + 135 * WK] = make_float2(Pm.x - iu.x, Pm.y - iu.y);
    }
}

// ---------------------------------------------------------------------------
// Kernels 3/4: per-block complex channel mix, 96 -> 96 over 16380 spatial pts.
// PHASE 0: out = relu(in @ w1 + b1); PHASE 1: out = softshrink(in @ w2 + b2).
// ---------------------------------------------------------------------------
template <int PHASE>
__global__ __launch_bounds__(192)
void k_mix(const float2* __restrict__ in, float2* __restrict__ out,
           const float* __restrict__ wgt, const float* __restrict__ bias) {
    const int TS = 64;
    __shared__ float2 ws[32 * BS];
    __shared__ float2 as[32 * TS];
    int k    = blockIdx.y;
    int s0   = blockIdx.x * TS;
    int o    = threadIdx.x;          // 0..95
    int half = threadIdx.y;          // 0..1
    int tid  = half * 96 + o;

    const float2* bb = (const float2*)bias;
    float2 bv = bb[k * BS + o];
    float accr[32], acci[32];
    #pragma unroll
    for (int j = 0; j < 32; j++) { accr[j] = bv.x; acci[j] = bv.y; }

    const float2* inb = in + (size_t)k * BS * S_;
    const float2* wb  = (const float2*)wgt + (size_t)k * BS * BS;

    for (int ic = 0; ic < BS; ic += 32) {
        for (int t = tid; t < 32 * BS; t += 192) {
            int i = t / BS, oo = t % BS;
            ws[t] = wb[(size_t)(ic + i) * BS + oo];
        }
        for (int t = tid; t < 32 * TS; t += 192) {
            int i = t / TS, sl = t % TS;
            int s = s0 + sl;
            as[t] = (s < S_) ? inb[(size_t)(ic + i) * S_ + s]
                             : make_float2(0.f, 0.f);
        }
        __syncthreads();
        #pragma unroll 4
        for (int i = 0; i < 32; i++) {
            float2 wv = ws[i * BS + o];
            const float2* arow = &as[i * TS + half * 32];
            #pragma unroll
            for (int j = 0; j < 32; j++) {
                float2 av = arow[j];
                accr[j] = fmaf(av.x, wv.x, fmaf(-av.y, wv.y, accr[j]));
                acci[j] = fmaf(av.y, wv.x, fmaf( av.x, wv.y, acci[j]));
            }
        }
        __syncthreads();
    }

    float2* ob = out + (size_t)k * BS * S_ + (size_t)o * S_;
    #pragma unroll
    for (int j = 0; j < 32; j++) {
        int s = s0 + half * 32 + j;
        if (s < S_) {
            float r = accr[j], m = acci[j];
            if (PHASE == 0) {
                r = fmaxf(r, 0.f);
                m = fmaxf(m, 0.f);
            } else {
                r = copysignf(fmaxf(fabsf(r) - LAM, 0.f), r);
                m = copysignf(fmaxf(fabsf(m) - LAM, 0.f), m);
            }
            ob[s] = make_float2(r, m);
        }
    }
}

// ---------------------------------------------------------------------------
// Kernel 6: inverse c2r DFT along W, paired outputs n <-> 360-n.
// x[n]     = 2*ORTHO*(0.5*X0r + U - V) + bias[n]
// x[360-n] = 2*ORTHO*(0.5*X0r + U + V) + bias[360-n]
//   with U = sum Xr*cos, V = sum Xi*sin over w=1..90. (DC imag ignored: c2r.)
// Threads n = 0..180; n=0,180 self-paired (V=0 there automatically).
// ---------------------------------------------------------------------------
__global__ __launch_bounds__(192)
void k_inv_w(const float* __restrict__ x, float* __restrict__ out) {
    __shared__ float2 X[WK];
    __shared__ float2 tw[W_];
    int row = blockIdx.x;                    // c*H + h
    const float2* sp = g_S1 + (size_t)row * WK;
    if (threadIdx.x < WK) X[threadIdx.x] = sp[threadIdx.x];
    for (int n = threadIdx.x; n < W_; n += 192) tw[n] = g_twWb[n];
    __syncthreads();
    const float* xp = x   + (size_t)row * W_;
    float*       op = out + (size_t)row * W_;
    int n = threadIdx.x;
    if (n <= H_) {
        float U = 0.f, V = 0.f;
        int idx = n;                          // w=1
        #pragma unroll 4
        for (int w = 1; w < WK; w++) {
            float2 e = tw[idx];              // (cos, +sin)
            float2 v = X[w];
            U = fmaf(v.x, e.x, U);
            V = fmaf(v.y, e.y, V);
            idx += n; if (idx >= W_) idx -= W_;
        }
        float base = 0.5f * X[0].x;
        float k2   = 2.0f * ORTHO;
        op[n] = fmaf(k2, base + U - V, xp[n]);
        if (n > 0 && n < H_) {
            int nm = W_ - n;
            op[nm] = fmaf(k2, base + U + V, xp[nm]);
        }
    }
}

// ---------------------------------------------------------------------------
extern "C" void kernel_launch(void* const* d_in, const int* in_sizes, int n_in,
                              void* d_out, int out_size) {
    const float* x  = (const float*)d_in[0];
    const float* w1 = (const float*)d_in[1];
    const float* b1 = (const float*)d_in[2];
    const float* w2 = (const float*)d_in[3];
    const float* b2 = (const float*)d_in[4];
    float* out = (float*)d_out;

    float2* S1; float2* S2;
    cudaGetSymbolAddress((void**)&S1, g_S1);
    cudaGetSymbolAddress((void**)&S2, g_S2);

    const int rows   = CH * H_;                    // 138240
    const int stiles = (S_ + 63) / 64;             // 256

    // 0. twiddle tables
    k_init_tw<<<1, 512>>>();
    // 1. forward W DFT (x -> S1), ortho-scaled
    k_fwd_w<<<rows, 128>>>(x);
    // 2. forward H DFT (S1 -> S2)
    k_fft_h<-1><<<dim3(WK / WT, CH), 256>>>(S1, S2);
    // 3. mix layer 1 + relu (S2 -> S1)
    k_mix<0><<<dim3(stiles, NB), dim3(96, 2)>>>(S2, S1, w1, b1);
    // 4. mix layer 2 + softshrink (S1 -> S2)
    k_mix<1><<<dim3(stiles, NB), dim3(96, 2)>>>(S1, S2, w2, b2);
    // 5. inverse H DFT (S2 -> S1)
    k_fft_h<+1><<<dim3(WK / WT, CH), 256>>>(S2, S1);
    // 6. inverse W c2r + residual (S1, x -> out), ortho-scaled
    k_inv_w<<<rows, 192>>>(x, out);
}

// round 6
// speedup vs baseline: 1.9786x; 1.9786x over previous
#include <cuda_runtime.h>
#include <math.h>

// Problem dims
#define CH   768
#define H_   180
#define W_   360
#define WK   91           // kept W modes (rfft bins 0..90; 91..180 provably zero)
#define NB   8
#define BS   96
#define S_   (H_ * WK)    // 16380 spectral points per channel
#define ROWS (CH * H_)    // 138240 spatial rows
#define KP   192          // padded folded-K for the W GEMMs
#define ORTHO 0.003928371006591931f   // 1/sqrt(180*360)
#define LAM  0.01f

// Scratch buffers
__device__ float2 g_S1[(size_t)CH * S_];
__device__ float2 g_S2[(size_t)CH * S_];
__device__ float2 g_PM[(size_t)KP * ROWS];   // folded (p,m), layout [n][row]

// Precomputed DFT matrices / twiddles
__device__ float2 g_Tf[KP * 96];   // fwd:  [n][w] = (cos(t n w), -sin(t n w)), t=2pi/360
__device__ float2 g_Ti[96 * KP];   // inv:  [w][n] = (cos, sin); w=0 -> (0.5, 0)
__device__ float2 g_twHf[H_];      // e^{-2pi i n/180}
__device__ float2 g_twHb[H_];      // e^{+2pi i n/180}

__device__ __forceinline__ float2 cmul(float2 a, float2 b) {
    return make_float2(fmaf(a.x, b.x, -a.y * b.y),
                       fmaf(a.x, b.y,  a.y * b.x));
}

// ---------------------------------------------------------------------------
// Init: DFT matrices + H twiddles.
// ---------------------------------------------------------------------------
__global__ void k_init_T() {
    int i = blockIdx.x * 256 + threadIdx.x;
    if (i < KP * 96) {                       // g_Tf  [n][w]
        int n = i / 96, w = i % 96;
        float2 v = make_float2(0.f, 0.f);
        if (n <= 180 && w <= 90) {
            float s, c;
            sincospif((float)((n * w) % 360) / 180.0f, &s, &c);
            v = make_float2(c, -s);
        }
        g_Tf[i] = v;
    }
    if (i < 96 * KP) {                       // g_Ti  [w][n]
        int w = i / KP, n = i % KP;
        float2 v = make_float2(0.f, 0.f);
        if (n <= 180 && w <= 90) {
            if (w == 0) v = make_float2(0.5f, 0.f);
            else {
                float s, c;
                sincospif((float)((n * w) % 360) / 180.0f, &s, &c);
                v = make_float2(c, s);
            }
        }
        g_Ti[i] = v;
    }
    if (i < H_) {
        float s, c;
        sincospif((float)i / 90.0f, &s, &c);
        g_twHf[i] = make_float2(c, -s);
        g_twHb[i] = make_float2(c,  s);
    }
}

// ---------------------------------------------------------------------------
// Fold: g_PM[n][row] = (p, m) with p[0]=x0, p[180]=x180, m[0]=m[180]=0,
// p[n]=x[n]+x[360-n], m[n]=x[n]-x[360-n] for 1<=n<=179; n>180 -> 0.
// Transposed via smem so both global sides are coalesced.
// ---------------------------------------------------------------------------
__global__ __launch_bounds__(256)
void k_fold(const float* __restrict__ x) {
    __shared__ float xs[32 * 361];           // [row][n], pad 361 (gcd(9,32)=1)
    int r0 = blockIdx.x * 32;
    for (int t = threadIdx.x; t < 32 * W_; t += 256) {
        int j = t / W_, n = t % W_;
        xs[j * 361 + n] = x[(size_t)(r0 + j) * W_ + n];
    }
    __syncthreads();
    for (int t = threadIdx.x; t < KP * 32; t += 256) {
        int n = t / 32, j = t % 32;
        float p = 0.f, m = 0.f;
        if (n == 0)        { p = xs[j * 361]; }
        else if (n == 180) { p = xs[j * 361 + 180]; }
        else if (n < 180) {
            float a = xs[j * 361 + n], b = xs[j * 361 + (W_ - n)];
            p = a + b; m = a - b;
        }
        g_PM[(size_t)n * ROWS + r0 + j] = make_float2(p, m);
    }
}

// ---------------------------------------------------------------------------
// Kernel 1: forward W r2c DFT as GEMM. Tile = 64 rows x 96 bins.
// re = sum_n p[n]*cos, im = sum_n m[n]*(-sin). Uniform K=192.
// ---------------------------------------------------------------------------
__global__ __launch_bounds__(192)
void k_fwd_w() {
    __shared__ float2 tws[32 * 96];                    // [i][w]
    __shared__ __align__(16) float2 as[32 * 66];       // [i][row], pad 66
    int r0   = blockIdx.x * 64;
    int o    = threadIdx.x;          // 0..95 (bins; >=91 compute-only)
    int half = threadIdx.y;          // 0..1 (row halves)
    int tid  = half * 96 + o;

    float re[32], im[32];
    #pragma unroll
    for (int j = 0; j < 32; j++) { re[j] = 0.f; im[j] = 0.f; }

    for (int nc = 0; nc < KP; nc += 32) {
        for (int t = tid; t < 32 * 96; t += 192)
            tws[t] = g_Tf[nc * 96 + t];
        for (int t = tid; t < 32 * 64; t += 192) {
            int i = t / 64, j = t % 64;
            as[i * 66 + j] = g_PM[(size_t)(nc + i) * ROWS + r0 + j];
        }
        __syncthreads();
        #pragma unroll 4
        for (int i = 0; i < 32; i++) {
            float2 wv = tws[i * 96 + o];               // (cos, -sin)
            const float4* ap = reinterpret_cast<const float4*>(&as[i * 66 + half * 32]);
            #pragma unroll
            for (int jp = 0; jp < 16; jp++) {
                float4 v = ap[jp];                     // p0,m0,p1,m1
                re[2*jp  ] = fmaf(v.x, wv.x, re[2*jp  ]);
                im[2*jp  ] = fmaf(v.y, wv.y, im[2*jp  ]);
                re[2*jp+1] = fmaf(v.z, wv.x, re[2*jp+1]);
                im[2*jp+1] = fmaf(v.w, wv.y, im[2*jp+1]);
            }
        }
        __syncthreads();
    }
    if (o < WK) {
        #pragma unroll
        for (int j = 0; j < 32; j++) {
            int row = r0 + half * 32 + j;
            g_S1[(size_t)row * WK + o] = make_float2(re[j] * ORTHO, im[j] * ORTHO);
        }
    }
}

// ---------------------------------------------------------------------------
// Kernels 2/5: 180-pt complex DFT along H, two-level DIT (radix-4 sharing).
// (unchanged from passing version)
// ---------------------------------------------------------------------------
#define WT 13
template <int SGN>
__global__ __launch_bounds__(256)
void k_fft_h(const float2* __restrict__ in, float2* __restrict__ out) {
    __shared__ float2 tile[H_ * WT];
    __shared__ float2 tw[H_];
    int c  = blockIdx.y;
    int w0 = blockIdx.x * WT;
    const float2* base = in + (size_t)c * S_;
    for (int i = threadIdx.x; i < H_ * WT; i += 256) {
        int h = i / WT, wl = i % WT;
        tile[i] = base[(size_t)h * WK + w0 + wl];
    }
    const float2* gt = (SGN < 0) ? g_twHf : g_twHb;
    for (int n = threadIdx.x; n < H_; n += 256) tw[n] = gt[n];
    __syncthreads();
    float2* ob = out + (size_t)c * S_;
    for (int it = threadIdx.x; it < 45 * WT; it += 256) {
        int k  = it / WT, wl = it % WT;
        int s4 = (4 * k) % H_;
        float2 PP = make_float2(0.f, 0.f), PQ = PP, QP = PP, QQ = PP;
        int idx = 0;
        #pragma unroll 5
        for (int r = 0; r < 45; r++) {
            float2 e  = tw[idx];
            float2 z0 = tile[(4 * r + 0) * WT + wl];
            float2 z1 = tile[(4 * r + 1) * WT + wl];
            float2 z2 = tile[(4 * r + 2) * WT + wl];
            float2 z3 = tile[(4 * r + 3) * WT + wl];
            PP.x = fmaf(z0.x, e.x, fmaf(-z0.y, e.y, PP.x));
            PP.y = fmaf(z0.x, e.y, fmaf( z0.y, e.x, PP.y));
            QP.x = fmaf(z1.x, e.x, fmaf(-z1.y, e.y, QP.x));
            QP.y = fmaf(z1.x, e.y, fmaf( z1.y, e.x, QP.y));
            PQ.x = fmaf(z2.x, e.x, fmaf(-z2.y, e.y, PQ.x));
            PQ.y = fmaf(z2.x, e.y, fmaf( z2.y, e.x, PQ.y));
            QQ.x = fmaf(z3.x, e.x, fmaf(-z3.y, e.y, QQ.x));
            QQ.y = fmaf(z3.x, e.y, fmaf( z3.y, e.x, QQ.y));
            idx += s4; if (idx >= H_) idx -= H_;
        }
        float2 w1t = tw[k];
        float2 w2t = tw[2 * k];
        float2 t2  = cmul(w2t, PQ);
        float2 t2q = cmul(w2t, QQ);
        float2 Pp = make_float2(PP.x + t2.x,  PP.y + t2.y);
        float2 Pm = make_float2(PP.x - t2.x,  PP.y - t2.y);
        float2 Qp = make_float2(QP.x + t2q.x, QP.y + t2q.y);
        float2 Qm = make_float2(QP.x - t2q.x, QP.y - t2q.y);
        float2 up = cmul(w1t, Qp);
        float2 um = cmul(w1t, Qm);
        float2 iu = make_float2((float)(-SGN) * um.y, (float)SGN * um.x);
        size_t o0 = (size_t)k * WK + w0 + wl;
        ob[o0           ] = make_float2(Pp.x + up.x, Pp.y + up.y);
        ob[o0 +  45 * WK] = make_float2(Pm.x + iu.x, Pm.y + iu.y);
        ob[o0 +  90 * WK] = make_float2(Pp.x - up.x, Pp.y - up.y);
        ob[o0 + 135 * WK] = make_float2(Pm.x - iu.x, Pm.y - iu.y);
    }
}

// ---------------------------------------------------------------------------
// Kernels 3/4: per-block complex channel mix (unchanged from passing version).
// ---------------------------------------------------------------------------
template <int PHASE>
__global__ __launch_bounds__(192)
void k_mix(const float2* __restrict__ in, float2* __restrict__ out,
           const float* __restrict__ wgt, const float* __restrict__ bias) {
    const int TS = 64;
    __shared__ float2 ws[32 * BS];
    __shared__ float2 as[32 * TS];
    int k    = blockIdx.y;
    int s0   = blockIdx.x * TS;
    int o    = threadIdx.x;
    int half = threadIdx.y;
    int tid  = half * 96 + o;

    const float2* bb = (const float2*)bias;
    float2 bv = bb[k * BS + o];
    float accr[32], acci[32];
    #pragma unroll
    for (int j = 0; j < 32; j++) { accr[j] = bv.x; acci[j] = bv.y; }

    const float2* inb = in + (size_t)k * BS * S_;
    const float2* wb  = (const float2*)wgt + (size_t)k * BS * BS;

    for (int ic = 0; ic < BS; ic += 32) {
        for (int t = tid; t < 32 * BS; t += 192) {
            int i = t / BS, oo = t % BS;
            ws[t] = wb[(size_t)(ic + i) * BS + oo];
        }
        for (int t = tid; t < 32 * TS; t += 192) {
            int i = t / TS, sl = t % TS;
            int s = s0 + sl;
            as[t] = (s < S_) ? inb[(size_t)(ic + i) * S_ + s]
                             : make_float2(0.f, 0.f);
        }
        __syncthreads();
        #pragma unroll 4
        for (int i = 0; i < 32; i++) {
            float2 wv = ws[i * BS + o];
            const float2* arow = &as[i * TS + half * 32];
            #pragma unroll
            for (int j = 0; j < 32; j++) {
                float2 av = arow[j];
                accr[j] = fmaf(av.x, wv.x, fmaf(-av.y, wv.y, accr[j]));
                acci[j] = fmaf(av.y, wv.x, fmaf( av.x, wv.y, acci[j]));
            }
        }
        __syncthreads();
    }

    float2* ob = out + (size_t)k * BS * S_ + (size_t)o * S_;
    #pragma unroll
    for (int j = 0; j < 32; j++) {
        int s = s0 + half * 32 + j;
        if (s < S_) {
            float r = accr[j], m = acci[j];
            if (PHASE == 0) {
                r = fmaxf(r, 0.f);
                m = fmaxf(m, 0.f);
            } else {
                r = copysignf(fmaxf(fabsf(r) - LAM, 0.f), r);
                m = copysignf(fmaxf(fabsf(m) - LAM, 0.f), m);
            }
            ob[s] = make_float2(r, m);
        }
    }
}

// ---------------------------------------------------------------------------
// Kernel 6: inverse c2r W DFT as GEMM. Tile = 32 rows x 181 outputs (paired).
// U = sum_w Xr*cos (incl. 0.5*X0r via w=0 column), V = sum_w Xi*sin.
// out[n] = 2*ORTHO*(U - V) + x[n]; out[360-n] = 2*ORTHO*(U + V) + x[360-n].
// ---------------------------------------------------------------------------
__global__ __launch_bounds__(192)
void k_inv_w(const float* __restrict__ x, float* __restrict__ out) {
    __shared__ float2 tws[16 * KP];                    // [i][n]
    __shared__ __align__(16) float2 xs[16 * 34];       // [i][row], pad 34
    int r0 = blockIdx.x * 32;
    int t  = threadIdx.x;            // n = t (t <= 180 active)

    float U[32], V[32];
    #pragma unroll
    for (int j = 0; j < 32; j++) { U[j] = 0.f; V[j] = 0.f; }

    for (int w0 = 0; w0 < 96; w0 += 16) {
        for (int tt = t; tt < 16 * KP; tt += 192)
            tws[tt] = g_Ti[w0 * KP + tt];
        for (int tt = t; tt < 16 * 32; tt += 192) {
            int i = tt % 16, j = tt / 16;
            int w = w0 + i;
            float2 v = (w < WK) ? g_S1[(size_t)(r0 + j) * WK + w]
                                : make_float2(0.f, 0.f);
            xs[i * 34 + j] = v;
        }
        __syncthreads();
        #pragma unroll 4
        for (int i = 0; i < 16; i++) {
            float2 wv = tws[i * KP + t];               // (cos, sin)
            const float4* xp4 = reinterpret_cast<const float4*>(&xs[i * 34]);
            #pragma unroll
            for (int jp = 0; jp < 16; jp++) {
                float4 v = xp4[jp];                    // Xr0,Xi0,Xr1,Xi1
                U[2*jp  ] = fmaf(v.x, wv.x, U[2*jp  ]);
                V[2*jp  ] = fmaf(v.y, wv.y, V[2*jp  ]);
                U[2*jp+1] = fmaf(v.z, wv.x, U[2*jp+1]);
                V[2*jp+1] = fmaf(v.w, wv.y, V[2*jp+1]);
            }
        }
        __syncthreads();
    }

    if (t <= 180) {
        const float k2 = 2.0f * ORTHO;
        #pragma unroll
        for (int j = 0; j < 32; j++) {
            size_t rb = (size_t)(r0 + j) * W_;
            out[rb + t] = fmaf(k2, U[j] - V[j], x[rb + t]);
            if (t > 0 && t < 180) {
                int nm = W_ - t;
                out[rb + nm] = fmaf(k2, U[j] + V[j], x[rb + nm]);
            }
        }
    }
}

// ---------------------------------------------------------------------------
extern "C" void kernel_launch(void* const* d_in, const int* in_sizes, int n_in,
                              void* d_out, int out_size) {
    const float* x  = (const float*)d_in[0];
    const float* w1 = (const float*)d_in[1];
    const float* b1 = (const float*)d_in[2];
    const float* w2 = (const float*)d_in[3];
    const float* b2 = (const float*)d_in[4];
    float* out = (float*)d_out;

    float2* S1; float2* S2;
    cudaGetSymbolAddress((void**)&S1, g_S1);
    cudaGetSymbolAddress((void**)&S2, g_S2);

    const int stiles = (S_ + 63) / 64;             // 256

    // 0. DFT matrices + twiddles
    k_init_T<<<(KP * 96 + 255) / 256, 256>>>();
    // 0b. fold x -> PM[n][row]
    k_fold<<<ROWS / 32, 256>>>(x);
    // 1. forward W DFT as GEMM (PM -> S1), ortho-scaled
    k_fwd_w<<<ROWS / 64, dim3(96, 2)>>>();
    // 2. forward H DFT (S1 -> S2)
    k_fft_h<-1><<<dim3(WK / WT, CH), 256>>>(S1, S2);
    // 3. mix layer 1 + relu (S2 -> S1)
    k_mix<0><<<dim3(stiles, NB), dim3(96, 2)>>>(S2, S1, w1, b1);
    // 4. mix layer 2 + softshrink (S1 -> S2)
    k_mix<1><<<dim3(stiles, NB), dim3(96, 2)>>>(S1, S2, w2, b2);
    // 5. inverse H DFT (S2 -> S1)
    k_fft_h<+1><<<dim3(WK / WT, CH), 256>>>(S2, S1);
    // 6. inverse W c2r as GEMM + residual (S1, x -> out)
    k_inv_w<<<ROWS / 32, 192>>>(x, out);
}

// round 10
// speedup vs baseline: 2.2934x; 1.1591x over previous
#include <cuda_runtime.h>
#include <math.h>

// Problem dims
#define CH   768
#define H_   180
#define W_   360
#define WK   91           // kept W modes (rfft bins 0..90; 91..180 provably zero)
#define NB   8
#define BS   96
#define S_   (H_ * WK)    // 16380 spectral points per channel
#define ROWS (CH * H_)    // 138240 spatial rows
#define KP   192          // padded folded-K for the W GEMMs
#define ORTHO 0.003928371006591931f   // 1/sqrt(180*360)
#define LAM  0.01f

// Scratch buffers
__device__ float2 g_S1[(size_t)CH * S_];
__device__ float2 g_S2[(size_t)CH * S_];
__device__ float2 g_PM[(size_t)KP * ROWS];   // folded (p,m), layout [n][row]

// Precomputed DFT matrices / twiddles
__device__ float2 g_Tf[KP * 96];   // fwd:  [n][w] = (cos(t n w), -sin(t n w)), t=2pi/360
__device__ float2 g_Ti[96 * KP];   // inv:  [w][n] = (cos, sin); w=0 -> (0.5, 0)
__device__ float2 g_twHf[H_];      // e^{-2pi i n/180}
__device__ float2 g_twHb[H_];      // e^{+2pi i n/180}

__device__ __forceinline__ float2 cmul(float2 a, float2 b) {
    return make_float2(fmaf(a.x, b.x, -a.y * b.y),
                       fmaf(a.x, b.y,  a.y * b.x));
}

// ---------------------------------------------------------------------------
// Init: DFT matrices + H twiddles.
// ---------------------------------------------------------------------------
__global__ void k_init_T() {
    int i = blockIdx.x * 256 + threadIdx.x;
    if (i < KP * 96) {                       // g_Tf  [n][w]
        int n = i / 96, w = i % 96;
        float2 v = make_float2(0.f, 0.f);
        if (n <= 180 && w <= 90) {
            float s, c;
            sincospif((float)((n * w) % 360) / 180.0f, &s, &c);
            v = make_float2(c, -s);
        }
        g_Tf[i] = v;
    }
    if (i < 96 * KP) {                       // g_Ti  [w][n]
        int w = i / KP, n = i % KP;
        float2 v = make_float2(0.f, 0.f);
        if (n <= 180 && w <= 90) {
            if (w == 0) v = make_float2(0.5f, 0.f);
            else {
                float s, c;
                sincospif((float)((n * w) % 360) / 180.0f, &s, &c);
                v = make_float2(c, s);
            }
        }
        g_Ti[i] = v;
    }
    if (i < H_) {
        float s, c;
        sincospif((float)i / 90.0f, &s, &c);
        g_twHf[i] = make_float2(c, -s);
        g_twHb[i] = make_float2(c,  s);
    }
}

// ---------------------------------------------------------------------------
// Fold: g_PM[n][row] = (p, m); p[0]=x0, p[180]=x180, m[0]=m[180]=0,
// p[n]=x[n]+x[360-n], m[n]=x[n]-x[360-n] for 1<=n<=179; n>180 -> 0.
// ---------------------------------------------------------------------------
__global__ __launch_bounds__(256)
void k_fold(const float* __restrict__ x) {
    __shared__ float xs[32 * 361];           // [row][n], pad 361
    int r0 = blockIdx.x * 32;
    for (int t = threadIdx.x; t < 32 * W_; t += 256) {
        int j = t / W_, n = t % W_;
        xs[j * 361 + n] = x[(size_t)(r0 + j) * W_ + n];
    }
    __syncthreads();
    for (int t = threadIdx.x; t < KP * 32; t += 256) {
        int n = t / 32, j = t % 32;
        float p = 0.f, m = 0.f;
        if (n == 0)        { p = xs[j * 361]; }
        else if (n == 180) { p = xs[j * 361 + 180]; }
        else if (n < 180) {
            float a = xs[j * 361 + n], b = xs[j * 361 + (W_ - n)];
            p = a + b; m = a - b;
        }
        g_PM[(size_t)n * ROWS + r0 + j] = make_float2(p, m);
    }
}

// ---------------------------------------------------------------------------
// Kernel 1: forward W r2c DFT as GEMM. Tile = 64 rows x 96 bins.
// ---------------------------------------------------------------------------
__global__ __launch_bounds__(192)
void k_fwd_w() {
    __shared__ float2 tws[32 * 96];                    // [i][w]
    __shared__ __align__(16) float2 as[32 * 66];       // [i][row], pad 66
    int r0   = blockIdx.x * 64;
    int o    = threadIdx.x;
    int half = threadIdx.y;
    int tid  = half * 96 + o;

    float re[32], im[32];
    #pragma unroll
    for (int j = 0; j < 32; j++) { re[j] = 0.f; im[j] = 0.f; }

    for (int nc = 0; nc < KP; nc += 32) {
        for (int t = tid; t < 32 * 96; t += 192)
            tws[t] = g_Tf[nc * 96 + t];
        for (int t = tid; t < 32 * 64; t += 192) {
            int i = t / 64, j = t % 64;
            as[i * 66 + j] = g_PM[(size_t)(nc + i) * ROWS + r0 + j];
        }
        __syncthreads();
        #pragma unroll 4
        for (int i = 0; i < 32; i++) {
            float2 wv = tws[i * 96 + o];               // (cos, -sin)
            const float4* ap = reinterpret_cast<const float4*>(&as[i * 66 + half * 32]);
            #pragma unroll
            for (int jp = 0; jp < 16; jp++) {
                float4 v = ap[jp];                     // p0,m0,p1,m1
                re[2*jp  ] = fmaf(v.x, wv.x, re[2*jp  ]);
                im[2*jp  ] = fmaf(v.y, wv.y, im[2*jp  ]);
                re[2*jp+1] = fmaf(v.z, wv.x, re[2*jp+1]);
                im[2*jp+1] = fmaf(v.w, wv.y, im[2*jp+1]);
            }
        }
        __syncthreads();
    }
    if (o < WK) {
        #pragma unroll
        for (int j = 0; j < 32; j++) {
            int row = r0 + half * 32 + j;
            g_S1[(size_t)row * WK + o] = make_float2(re[j] * ORTHO, im[j] * ORTHO);
        }
    }
}

// ---------------------------------------------------------------------------
// Kernels 2/5: 180-pt complex DFT along H, radix-4 sharing + 3-way k-blocking.
// Thread handles k in {k0, k0+15, k0+30}; twiddles for the extra k's come from
// cmul by omega = W^60 (period 3 in r), so z loads are amortized 3x.
// ---------------------------------------------------------------------------
#define WT 13
template <int SGN>
__global__ __launch_bounds__(224)
void k_fft_h(const float2* __restrict__ in, float2* __restrict__ out) {
    __shared__ float2 tile[H_ * WT];
    __shared__ float2 tw[H_];
    int c  = blockIdx.y;
    int w0 = blockIdx.x * WT;
    const float2* base = in + (size_t)c * S_;
    for (int i = threadIdx.x; i < H_ * WT; i += 224) {
        int h = i / WT, wl = i % WT;
        tile[i] = base[(size_t)h * WK + w0 + wl];
    }
    const float2* gt = (SGN < 0) ? g_twHf : g_twHb;
    for (int n = threadIdx.x; n < H_; n += 224) tw[n] = gt[n];
    __syncthreads();

    int tid = threadIdx.x;
    if (tid < 195) {
        int k0 = tid / WT, wl = tid % WT;    // k0 in [0,15)
        float2 w60  = tw[60];                // omega   = W^60
        float2 w120 = tw[120];               // omega^2 = W^120
        int s4 = 4 * k0;                     // <= 56

        // A[t][j] = sum_r z[4r+j] * W^{4 r (k0+15t)}
        float2 A[3][4];
        #pragma unroll
        for (int t = 0; t < 3; t++)
            #pragma unroll
            for (int j = 0; j < 4; j++) A[t][j] = make_float2(0.f, 0.f);

        int idx = 0;
        #pragma unroll 3
        for (int q = 0; q < 15; q++) {
            #pragma unroll
            for (int u = 0; u < 3; u++) {
                int r = 3 * q + u;
                float2 e0 = tw[idx];
                float2 e1, e2;
                if (u == 0)      { e1 = e0; e2 = e0; }
                else if (u == 1) { e1 = cmul(e0, w60);  e2 = cmul(e0, w120); }
                else             { e1 = cmul(e0, w120); e2 = cmul(e0, w60);  }
                float2 z0 = tile[(4 * r + 0) * WT + wl];
                float2 z1 = tile[(4 * r + 1) * WT + wl];
                float2 z2 = tile[(4 * r + 2) * WT + wl];
                float2 z3 = tile[(4 * r + 3) * WT + wl];
                #pragma unroll
                for (int t = 0; t < 3; t++) {
                    float2 e = (t == 0) ? e0 : (t == 1) ? e1 : e2;
                    A[t][0].x = fmaf(z0.x, e.x, fmaf(-z0.y, e.y, A[t][0].x));
                    A[t][0].y = fmaf(z0.x, e.y, fmaf( z0.y, e.x, A[t][0].y));
                    A[t][1].x = fmaf(z1.x, e.x, fmaf(-z1.y, e.y, A[t][1].x));
                    A[t][1].y = fmaf(z1.x, e.y, fmaf( z1.y, e.x, A[t][1].y));
                    A[t][2].x = fmaf(z2.x, e.x, fmaf(-z2.y, e.y, A[t][2].x));
                    A[t][2].y = fmaf(z2.x, e.y, fmaf( z2.y, e.x, A[t][2].y));
                    A[t][3].x = fmaf(z3.x, e.x, fmaf(-z3.y, e.y, A[t][3].x));
                    A[t][3].y = fmaf(z3.x, e.y, fmaf( z3.y, e.x, A[t][3].y));
                }
                idx += s4; if (idx >= H_) idx -= H_;
            }
        }

        float2* ob = out + (size_t)c * S_;
        #pragma unroll
        for (int t = 0; t < 3; t++) {
            int kt = k0 + 15 * t;
            float2 PP = A[t][0], QP = A[t][1], PQ = A[t][2], QQ = A[t][3];
            float2 w1t = tw[kt];
            float2 w2t = tw[2 * kt];
            float2 t2  = cmul(w2t, PQ);
            float2 t2q = cmul(w2t, QQ);
            float2 Pp = make_float2(PP.x + t2.x,  PP.y + t2.y);
            float2 Pm = make_float2(PP.x - t2.x,  PP.y - t2.y);
            float2 Qp = make_float2(QP.x + t2q.x, QP.y + t2q.y);
            float2 Qm = make_float2(QP.x - t2q.x, QP.y - t2q.y);
            float2 up = cmul(w1t, Qp);
            float2 um = cmul(w1t, Qm);
            float2 iu = make_float2((float)(-SGN) * um.y, (float)SGN * um.x);
            size_t o0 = (size_t)kt * WK + w0 + wl;
            ob[o0           ] = make_float2(Pp.x + up.x, Pp.y + up.y);
            ob[o0 +  45 * WK] = make_float2(Pm.x + iu.x, Pm.y + iu.y);
            ob[o0 +  90 * WK] = make_float2(Pp.x - up.x, Pp.y - up.y);
            ob[o0 + 135 * WK] = make_float2(Pm.x - iu.x, Pm.y - iu.y);
        }
    }
}

// ---------------------------------------------------------------------------
// Kernels 3+4 fused: o2 = softshrink(w2 @ relu(w1 @ in + b1) + b2).
// Intermediate o1 lives in shared ([channel][spatial], pad 66). Dynamic smem.
// ---------------------------------------------------------------------------
__global__ __launch_bounds__(192)
void k_mix_f(const float2* __restrict__ in, float2* __restrict__ out,
             const float* __restrict__ w1_, const float* __restrict__ b1_,
             const float* __restrict__ w2_, const float* __restrict__ b2_) {
    const int TS = 64;
    extern __shared__ float2 sm[];
    float2* ws  = sm;                        // 32*96  = 24.6 KB
    float2* as  = sm + 32 * 96;              // 32*64  = 16.4 KB
    float2* o1s = sm + 32 * 96 + 32 * TS;    // 96*66  = 50.7 KB
    int k    = blockIdx.y;
    int s0   = blockIdx.x * TS;
    int o    = threadIdx.x;          // 0..95
    int half = threadIdx.y;          // 0..1
    int tid  = half * 96 + o;

    float accr[32], acci[32];
    {
        float2 bv = ((const float2*)b1_)[k * BS + o];
        #pragma unroll
        for (int j = 0; j < 32; j++) { accr[j] = bv.x; acci[j] = bv.y; }
    }

    const float2* inb = in + (size_t)k * BS * S_;
    const float2* wb1 = (const float2*)w1_ + (size_t)k * BS * BS;

    // ---- GEMM 1: o1 = relu(in @ w1 + b1) ----
    for (int ic = 0; ic < BS; ic += 32) {
        for (int t = tid; t < 32 * BS; t += 192)
            ws[t] = wb1[(size_t)ic * BS + t];
        for (int t = tid; t < 32 * TS; t += 192) {
            int i = t / TS, sl = t % TS;
            int s = s0 + sl;
            as[t] = (s < S_) ? inb[(size_t)(ic + i) * S_ + s]
                             : make_float2(0.f, 0.f);
        }
        __syncthreads();
        #pragma unroll 4
        for (int i = 0; i < 32; i++) {
            float2 wv = ws[i * BS + o];
            const float4* ap = reinterpret_cast<const float4*>(&as[i * TS + half * 32]);
            #pragma unroll
            for (int jp = 0; jp < 16; jp++) {
                float4 v = ap[jp];                     // r0,i0,r1,i1
                accr[2*jp  ] = fmaf(v.x, wv.x, fmaf(-v.y, wv.y, accr[2*jp  ]));
                acci[2*jp  ] = fmaf(v.y, wv.x, fmaf( v.x, wv.y, acci[2*jp  ]));
                accr[2*jp+1] = fmaf(v.z, wv.x, fmaf(-v.w, wv.y, accr[2*jp+1]));
                acci[2*jp+1] = fmaf(v.w, wv.x, fmaf( v.z, wv.y, acci[2*jp+1]));
            }
        }
        __syncthreads();
    }

    // relu -> o1s [channel][spatial]
    #pragma unroll
    for (int j = 0; j < 32; j++)
        o1s[o * 66 + half * 32 + j] =
            make_float2(fmaxf(accr[j], 0.f), fmaxf(acci[j], 0.f));
    {
        float2 bv = ((const float2*)b2_)[k * BS + o];
        #pragma unroll
        for (int j = 0; j < 32; j++) { accr[j] = bv.x; acci[j] = bv.y; }
    }
    __syncthreads();

    // ---- GEMM 2: o2 = o1 @ w2 + b2 (A operand from smem) ----
    const float2* wb2 = (const float2*)w2_ + (size_t)k * BS * BS;
    for (int ic = 0; ic < BS; ic += 32) {
        for (int t = tid; t < 32 * BS; t += 192)
            ws[t] = wb2[(size_t)ic * BS + t];
        __syncthreads();
        #pragma unroll 4
        for (int i = 0; i < 32; i++) {
            float2 wv = ws[i * BS + o];
            const float4* ap =
                reinterpret_cast<const float4*>(&o1s[(ic + i) * 66 + half * 32]);
            #pragma unroll
            for (int jp = 0; jp < 16; jp++) {
                float4 v = ap[jp];
                accr[2*jp  ] = fmaf(v.x, wv.x, fmaf(-v.y, wv.y, accr[2*jp  ]));
                acci[2*jp  ] = fmaf(v.y, wv.x, fmaf( v.x, wv.y, acci[2*jp  ]));
                accr[2*jp+1] = fmaf(v.z, wv.x, fmaf(-v.w, wv.y, accr[2*jp+1]));
                acci[2*jp+1] = fmaf(v.w, wv.x, fmaf( v.z, wv.y, acci[2*jp+1]));
            }
        }
        __syncthreads();
    }

    // softshrink epilogue
    float2* ob = out + (size_t)k * BS * S_ + (size_t)o * S_;
    #pragma unroll
    for (int j = 0; j < 32; j++) {
        int s = s0 + half * 32 + j;
        if (s < S_) {
            float r = accr[j], m = acci[j];
            r = copysignf(fmaxf(fabsf(r) - LAM, 0.f), r);
            m = copysignf(fmaxf(fabsf(m) - LAM, 0.f), m);
            ob[s] = make_float2(r, m);
        }
    }
}

// ---------------------------------------------------------------------------
// Kernel 6: inverse c2r W DFT as GEMM. Reads g_S2 (inverse-H output).
// ---------------------------------------------------------------------------
__global__ __launch_bounds__(192)
void k_inv_w(const float* __restrict__ x, float* __restrict__ out) {
    __shared__ float2 tws[16 * KP];                    // [i][n]
    __shared__ __align__(16) float2 xs[16 * 34];       // [i][row], pad 34
    int r0 = blockIdx.x * 32;
    int t  = threadIdx.x;

    float U[32], V[32];
    #pragma unroll
    for (int j = 0; j < 32; j++) { U[j] = 0.f; V[j] = 0.f; }

    for (int w0 = 0; w0 < 96; w0 += 16) {
        for (int tt = t; tt < 16 * KP; tt += 192)
            tws[tt] = g_Ti[w0 * KP + tt];
        for (int tt = t; tt < 16 * 32; tt += 192) {
            int i = tt % 16, j = tt / 16;
            int w = w0 + i;
            float2 v = (w < WK) ? g_S2[(size_t)(r0 + j) * WK + w]
                                : make_float2(0.f, 0.f);
            xs[i * 34 + j] = v;
        }
        __syncthreads();
        #pragma unroll 4
        for (int i = 0; i < 16; i++) {
            float2 wv = tws[i * KP + t];               // (cos, sin)
            const float4* xp4 = reinterpret_cast<const float4*>(&xs[i * 34]);
            #pragma unroll
            for (int jp = 0; jp < 16; jp++) {
                float4 v = xp4[jp];                    // Xr0,Xi0,Xr1,Xi1
                U[2*jp  ] = fmaf(v.x, wv.x, U[2*jp  ]);
                V[2*jp  ] = fmaf(v.y, wv.y, V[2*jp  ]);
                U[2*jp+1] = fmaf(v.z, wv.x, U[2*jp+1]);
                V[2*jp+1] = fmaf(v.w, wv.y, V[2*jp+1]);
            }
        }
        __syncthreads();
    }

    if (t <= 180) {
        const float k2 = 2.0f * ORTHO;
        #pragma unroll
        for (int j = 0; j < 32; j++) {
            size_t rb = (size_t)(r0 + j) * W_;
            out[rb + t] = fmaf(k2, U[j] - V[j], x[rb + t]);
            if (t > 0 && t < 180) {
                int nm = W_ - t;
                out[rb + nm] = fmaf(k2, U[j] + V[j], x[rb + nm]);
            }
        }
    }
}

// ---------------------------------------------------------------------------
extern "C" void kernel_launch(void* const* d_in, const int* in_sizes, int n_in,
                              void* d_out, int out_size) {
    const float* x  = (const float*)d_in[0];
    const float* w1 = (const float*)d_in[1];
    const float* b1 = (const float*)d_in[2];
    const float* w2 = (const float*)d_in[3];
    const float* b2 = (const float*)d_in[4];
    float* out = (float*)d_out;

    float2* S1; float2* S2;
    cudaGetSymbolAddress((void**)&S1, g_S1);
    cudaGetSymbolAddress((void**)&S2, g_S2);

    const int stiles = (S_ + 63) / 64;             // 256
    const int mix_smem = (32 * 96 + 32 * 64 + 96 * 66) * (int)sizeof(float2);

    cudaFuncSetAttribute(k_mix_f,
                         cudaFuncAttributeMaxDynamicSharedMemorySize, mix_smem);

    // 0. DFT matrices + twiddles
    k_init_T<<<(KP * 96 + 255) / 256, 256>>>();
    // 0b. fold x -> PM[n][row]
    k_fold<<<ROWS / 32, 256>>>(x);
    // 1. forward W DFT as GEMM (PM -> S1), ortho-scaled
    k_fwd_w<<<ROWS / 64, dim3(96, 2)>>>();
    // 2. forward H DFT (S1 -> S2)
    k_fft_h<-1><<<dim3(WK / WT, CH), 224>>>(S1, S2);
    // 3+4. fused mix: relu(w1) then softshrink(w2)  (S2 -> S1)
    k_mix_f<<<dim3(stiles, NB), dim3(96, 2), mix_smem>>>(S2, S1, w1, b1, w2, b2);
    // 5. inverse H DFT (S1 -> S2)
    k_fft_h<+1><<<dim3(WK / WT, CH), 224>>>(S1, S2);
    // 6. inverse W c2r as GEMM + residual (S2, x -> out)
    k_inv_w<<<ROWS / 32, 192>>>(x, out);
}

// round 11
// speedup vs baseline: 2.4757x; 1.0795x over previous
#include <cuda_runtime.h>
#include <math.h>

// Problem dims
#define CH   768
#define H_   180
#define W_   360
#define WK   91           // kept W modes (rfft bins 0..90; 91..180 provably zero)
#define NB   8
#define BS   96
#define S_   (H_ * WK)    // 16380 spectral points per channel
#define ROWS (CH * H_)    // 138240 spatial rows
#define KP   192          // padded folded-K for the W GEMMs
#define ORTHO 0.003928371006591931f   // 1/sqrt(180*360)
#define LAM  0.01f

// Scratch buffers
__device__ float2 g_S1[(size_t)CH * S_];
__device__ float2 g_S2[(size_t)CH * S_];
__device__ float2 g_PM[(size_t)KP * ROWS];   // folded (p,m), layout [n][row]

// Precomputed DFT matrices / twiddles
__device__ float2 g_Tf[KP * 96];   // fwd:  [n][w] = (cos(t n w), -sin(t n w)), t=2pi/360
__device__ float2 g_Ti[96 * KP];   // inv:  [w][n] = (cos, sin); w=0 -> (0.5, 0)
__device__ float2 g_twHf[H_];      // e^{-2pi i n/180}
__device__ float2 g_twHb[H_];      // e^{+2pi i n/180}

__device__ __forceinline__ float2 cmul(float2 a, float2 b) {
    return make_float2(fmaf(a.x, b.x, -a.y * b.y),
                       fmaf(a.x, b.y,  a.y * b.x));
}

// ---------------------------------------------------------------------------
// Init: DFT matrices + H twiddles.
// ---------------------------------------------------------------------------
__global__ void k_init_T() {
    int i = blockIdx.x * 256 + threadIdx.x;
    if (i < KP * 96) {                       // g_Tf  [n][w]
        int n = i / 96, w = i % 96;
        float2 v = make_float2(0.f, 0.f);
        if (n <= 180 && w <= 90) {
            float s, c;
            sincospif((float)((n * w) % 360) / 180.0f, &s, &c);
            v = make_float2(c, -s);
        }
        g_Tf[i] = v;
    }
    if (i < 96 * KP) {                       // g_Ti  [w][n]
        int w = i / KP, n = i % KP;
        float2 v = make_float2(0.f, 0.f);
        if (n <= 180 && w <= 90) {
            if (w == 0) v = make_float2(0.5f, 0.f);
            else {
                float s, c;
                sincospif((float)((n * w) % 360) / 180.0f, &s, &c);
                v = make_float2(c, s);
            }
        }
        g_Ti[i] = v;
    }
    if (i < H_) {
        float s, c;
        sincospif((float)i / 90.0f, &s, &c);
        g_twHf[i] = make_float2(c, -s);
        g_twHb[i] = make_float2(c,  s);
    }
}

// ---------------------------------------------------------------------------
// Fold: g_PM[n][row] = (p, m); p[0]=x0, p[180]=x180, m[0]=m[180]=0,
// p[n]=x[n]+x[360-n], m[n]=x[n]-x[360-n] for 1<=n<=179; n>180 -> 0.
// ---------------------------------------------------------------------------
__global__ __launch_bounds__(256)
void k_fold(const float* __restrict__ x) {
    __shared__ float xs[32 * 361];           // [row][n], pad 361
    int r0 = blockIdx.x * 32;
    for (int t = threadIdx.x; t < 32 * W_; t += 256) {
        int j = t / W_, n = t % W_;
        xs[j * 361 + n] = x[(size_t)(r0 + j) * W_ + n];
    }
    __syncthreads();
    for (int t = threadIdx.x; t < KP * 32; t += 256) {
        int n = t / 32, j = t % 32;
        float p = 0.f, m = 0.f;
        if (n == 0)        { p = xs[j * 361]; }
        else if (n == 180) { p = xs[j * 361 + 180]; }
        else if (n < 180) {
            float a = xs[j * 361 + n], b = xs[j * 361 + (W_ - n)];
            p = a + b; m = a - b;
        }
        g_PM[(size_t)n * ROWS + r0 + j] = make_float2(p, m);
    }
}

// ---------------------------------------------------------------------------
// Kernel 1: forward W r2c DFT as GEMM. Tile = 64 rows x 96 bins.
// Threads (48,4): each owns bins {x, x+48} and 16 rows [16y, 16y+16).
// ---------------------------------------------------------------------------
__global__ __launch_bounds__(192)
void k_fwd_w() {
    __shared__ float2 tws[32 * 96];                    // [i][w]
    __shared__ __align__(16) float2 as[32 * 66];       // [i][row], pad 66
    int r0  = blockIdx.x * 64;
    int x_  = threadIdx.x;           // 0..47
    int y_  = threadIdx.y;           // 0..3
    int tid = x_ + 48 * y_;

    float re[2][16], im[2][16];
    #pragma unroll
    for (int oo = 0; oo < 2; oo++)
        #pragma unroll
        for (int j = 0; j < 16; j++) { re[oo][j] = 0.f; im[oo][j] = 0.f; }

    for (int nc = 0; nc < KP; nc += 32) {
        for (int t = tid; t < 32 * 96; t += 192)
            tws[t] = g_Tf[nc * 96 + t];
        for (int t = tid; t < 32 * 64; t += 192) {
            int i = t / 64, j = t % 64;
            as[i * 66 + j] = g_PM[(size_t)(nc + i) * ROWS + r0 + j];
        }
        __syncthreads();
        #pragma unroll 4
        for (int i = 0; i < 32; i++) {
            float2 wv0 = tws[i * 96 + x_];             // (cos, -sin)
            float2 wv1 = tws[i * 96 + x_ + 48];
            const float4* ap = reinterpret_cast<const float4*>(&as[i * 66 + y_ * 16]);
            #pragma unroll
            for (int jp = 0; jp < 8; jp++) {
                float4 v = ap[jp];                     // p0,m0,p1,m1
                re[0][2*jp  ] = fmaf(v.x, wv0.x, re[0][2*jp  ]);
                im[0][2*jp  ] = fmaf(v.y, wv0.y, im[0][2*jp  ]);
                re[0][2*jp+1] = fmaf(v.z, wv0.x, re[0][2*jp+1]);
                im[0][2*jp+1] = fmaf(v.w, wv0.y, im[0][2*jp+1]);
                re[1][2*jp  ] = fmaf(v.x, wv1.x, re[1][2*jp  ]);
                im[1][2*jp  ] = fmaf(v.y, wv1.y, im[1][2*jp  ]);
                re[1][2*jp+1] = fmaf(v.z, wv1.x, re[1][2*jp+1]);
                im[1][2*jp+1] = fmaf(v.w, wv1.y, im[1][2*jp+1]);
            }
        }
        __syncthreads();
    }
    #pragma unroll
    for (int oo = 0; oo < 2; oo++) {
        int o = x_ + 48 * oo;
        if (o < WK) {
            #pragma unroll
            for (int j = 0; j < 16; j++) {
                int row = r0 + y_ * 16 + j;
                g_S1[(size_t)row * WK + o] =
                    make_float2(re[oo][j] * ORTHO, im[oo][j] * ORTHO);
            }
        }
    }
}

// ---------------------------------------------------------------------------
// Kernels 2/5: 180-pt complex DFT along H, radix-4 sharing + 3-way k-blocking.
// (unchanged from R10 passing version)
// ---------------------------------------------------------------------------
#define WT 13
template <int SGN>
__global__ __launch_bounds__(224)
void k_fft_h(const float2* __restrict__ in, float2* __restrict__ out) {
    __shared__ float2 tile[H_ * WT];
    __shared__ float2 tw[H_];
    int c  = blockIdx.y;
    int w0 = blockIdx.x * WT;
    const float2* base = in + (size_t)c * S_;
    for (int i = threadIdx.x; i < H_ * WT; i += 224) {
        int h = i / WT, wl = i % WT;
        tile[i] = base[(size_t)h * WK + w0 + wl];
    }
    const float2* gt = (SGN < 0) ? g_twHf : g_twHb;
    for (int n = threadIdx.x; n < H_; n += 224) tw[n] = gt[n];
    __syncthreads();

    int tid = threadIdx.x;
    if (tid < 195) {
        int k0 = tid / WT, wl = tid % WT;    // k0 in [0,15)
        float2 w60  = tw[60];                // omega   = W^60
        float2 w120 = tw[120];               // omega^2 = W^120
        int s4 = 4 * k0;                     // <= 56

        float2 A[3][4];
        #pragma unroll
        for (int t = 0; t < 3; t++)
            #pragma unroll
            for (int j = 0; j < 4; j++) A[t][j] = make_float2(0.f, 0.f);

        int idx = 0;
        #pragma unroll 3
        for (int q = 0; q < 15; q++) {
            #pragma unroll
            for (int u = 0; u < 3; u++) {
                int r = 3 * q + u;
                float2 e0 = tw[idx];
                float2 e1, e2;
                if (u == 0)      { e1 = e0; e2 = e0; }
                else if (u == 1) { e1 = cmul(e0, w60);  e2 = cmul(e0, w120); }
                else             { e1 = cmul(e0, w120); e2 = cmul(e0, w60);  }
                float2 z0 = tile[(4 * r + 0) * WT + wl];
                float2 z1 = tile[(4 * r + 1) * WT + wl];
                float2 z2 = tile[(4 * r + 2) * WT + wl];
                float2 z3 = tile[(4 * r + 3) * WT + wl];
                #pragma unroll
                for (int t = 0; t < 3; t++) {
                    float2 e = (t == 0) ? e0 : (t == 1) ? e1 : e2;
                    A[t][0].x = fmaf(z0.x, e.x, fmaf(-z0.y, e.y, A[t][0].x));
                    A[t][0].y = fmaf(z0.x, e.y, fmaf( z0.y, e.x, A[t][0].y));
                    A[t][1].x = fmaf(z1.x, e.x, fmaf(-z1.y, e.y, A[t][1].x));
                    A[t][1].y = fmaf(z1.x, e.y, fmaf( z1.y, e.x, A[t][1].y));
                    A[t][2].x = fmaf(z2.x, e.x, fmaf(-z2.y, e.y, A[t][2].x));
                    A[t][2].y = fmaf(z2.x, e.y, fmaf( z2.y, e.x, A[t][2].y));
                    A[t][3].x = fmaf(z3.x, e.x, fmaf(-z3.y, e.y, A[t][3].x));
                    A[t][3].y = fmaf(z3.x, e.y, fmaf( z3.y, e.x, A[t][3].y));
                }
                idx += s4; if (idx >= H_) idx -= H_;
            }
        }

        float2* ob = out + (size_t)c * S_;
        #pragma unroll
        for (int t = 0; t < 3; t++) {
            int kt = k0 + 15 * t;
            float2 PP = A[t][0], QP = A[t][1], PQ = A[t][2], QQ = A[t][3];
            float2 w1t = tw[kt];
            float2 w2t = tw[2 * kt];
            float2 t2  = cmul(w2t, PQ);
            float2 t2q = cmul(w2t, QQ);
            float2 Pp = make_float2(PP.x + t2.x,  PP.y + t2.y);
            float2 Pm = make_float2(PP.x - t2.x,  PP.y - t2.y);
            float2 Qp = make_float2(QP.x + t2q.x, QP.y + t2q.y);
            float2 Qm = make_float2(QP.x - t2q.x, QP.y - t2q.y);
            float2 up = cmul(w1t, Qp);
            float2 um = cmul(w1t, Qm);
            float2 iu = make_float2((float)(-SGN) * um.y, (float)SGN * um.x);
            size_t o0 = (size_t)kt * WK + w0 + wl;
            ob[o0           ] = make_float2(Pp.x + up.x, Pp.y + up.y);
            ob[o0 +  45 * WK] = make_float2(Pm.x + iu.x, Pm.y + iu.y);
            ob[o0 +  90 * WK] = make_float2(Pp.x - up.x, Pp.y - up.y);
            ob[o0 + 135 * WK] = make_float2(Pm.x - iu.x, Pm.y - iu.y);
        }
    }
}

// ---------------------------------------------------------------------------
// Kernels 3+4 fused: o2 = softshrink(w2 @ relu(w1 @ in + b1) + b2).
// Threads (48,4): each owns channels {x, x+48} and 16 spatial [16y, 16y+16).
// ---------------------------------------------------------------------------
__global__ __launch_bounds__(192)
void k_mix_f(const float2* __restrict__ in, float2* __restrict__ out,
             const float* __restrict__ w1_, const float* __restrict__ b1_,
             const float* __restrict__ w2_, const float* __restrict__ b2_) {
    const int TS = 64;
    extern __shared__ float2 sm[];
    float2* ws  = sm;                        // 32*96  = 24.6 KB
    float2* as  = sm + 32 * 96;              // 32*64  = 16.4 KB
    float2* o1s = sm + 32 * 96 + 32 * TS;    // 96*66  = 50.7 KB
    int k   = blockIdx.y;
    int s0  = blockIdx.x * TS;
    int x_  = threadIdx.x;           // 0..47
    int y_  = threadIdx.y;           // 0..3
    int tid = x_ + 48 * y_;
    int jb  = y_ * 16;

    float ar[2][16], ai[2][16];
    {
        const float2* bb = (const float2*)b1_;
        float2 bv0 = bb[k * BS + x_];
        float2 bv1 = bb[k * BS + x_ + 48];
        #pragma unroll
        for (int j = 0; j < 16; j++) {
            ar[0][j] = bv0.x; ai[0][j] = bv0.y;
            ar[1][j] = bv1.x; ai[1][j] = bv1.y;
        }
    }

    const float2* inb = in + (size_t)k * BS * S_;
    const float2* wb1 = (const float2*)w1_ + (size_t)k * BS * BS;

    // ---- GEMM 1: o1 = relu(in @ w1 + b1) ----
    for (int ic = 0; ic < BS; ic += 32) {
        for (int t = tid; t < 32 * BS; t += 192)
            ws[t] = wb1[(size_t)ic * BS + t];
        for (int t = tid; t < 32 * TS; t += 192) {
            int i = t / TS, sl = t % TS;
            int s = s0 + sl;
            as[t] = (s < S_) ? inb[(size_t)(ic + i) * S_ + s]
                             : make_float2(0.f, 0.f);
        }
        __syncthreads();
        #pragma unroll 4
        for (int i = 0; i < 32; i++) {
            float2 wv0 = ws[i * BS + x_];
            float2 wv1 = ws[i * BS + x_ + 48];
            const float4* ap = reinterpret_cast<const float4*>(&as[i * TS + jb]);
            #pragma unroll
            for (int jp = 0; jp < 8; jp++) {
                float4 v = ap[jp];                     // r0,i0,r1,i1
                ar[0][2*jp  ] = fmaf(v.x, wv0.x, fmaf(-v.y, wv0.y, ar[0][2*jp  ]));
                ai[0][2*jp  ] = fmaf(v.y, wv0.x, fmaf( v.x, wv0.y, ai[0][2*jp  ]));
                ar[0][2*jp+1] = fmaf(v.z, wv0.x, fmaf(-v.w, wv0.y, ar[0][2*jp+1]));
                ai[0][2*jp+1] = fmaf(v.w, wv0.x, fmaf( v.z, wv0.y, ai[0][2*jp+1]));
                ar[1][2*jp  ] = fmaf(v.x, wv1.x, fmaf(-v.y, wv1.y, ar[1][2*jp  ]));
                ai[1][2*jp  ] = fmaf(v.y, wv1.x, fmaf( v.x, wv1.y, ai[1][2*jp  ]));
                ar[1][2*jp+1] = fmaf(v.z, wv1.x, fmaf(-v.w, wv1.y, ar[1][2*jp+1]));
                ai[1][2*jp+1] = fmaf(v.w, wv1.x, fmaf( v.z, wv1.y, ai[1][2*jp+1]));
            }
        }
        __syncthreads();
    }

    // relu -> o1s [channel][spatial]
    #pragma unroll
    for (int oo = 0; oo < 2; oo++) {
        int o = x_ + 48 * oo;
        #pragma unroll
        for (int j = 0; j < 16; j++)
            o1s[o * 66 + jb + j] =
                make_float2(fmaxf(ar[oo][j], 0.f), fmaxf(ai[oo][j], 0.f));
    }
    {
        const float2* bb = (const float2*)b2_;
        float2 bv0 = bb[k * BS + x_];
        float2 bv1 = bb[k * BS + x_ + 48];
        #pragma unroll
        for (int j = 0; j < 16; j++) {
            ar[0][j] = bv0.x; ai[0][j] = bv0.y;
            ar[1][j] = bv1.x; ai[1][j] = bv1.y;
        }
    }
    __syncthreads();

    // ---- GEMM 2: o2 = o1 @ w2 + b2 (A operand from smem) ----
    const float2* wb2 = (const float2*)w2_ + (size_t)k * BS * BS;
    for (int ic = 0; ic < BS; ic += 32) {
        for (int t = tid; t < 32 * BS; t += 192)
            ws[t] = wb2[(size_t)ic * BS + t];
        __syncthreads();
        #pragma unroll 4
        for (int i = 0; i < 32; i++) {
            float2 wv0 = ws[i * BS + x_];
            float2 wv1 = ws[i * BS + x_ + 48];
            const float4* ap =
                reinterpret_cast<const float4*>(&o1s[(ic + i) * 66 + jb]);
            #pragma unroll
            for (int jp = 0; jp < 8; jp++) {
                float4 v = ap[jp];
                ar[0][2*jp  ] = fmaf(v.x, wv0.x, fmaf(-v.y, wv0.y, ar[0][2*jp  ]));
                ai[0][2*jp  ] = fmaf(v.y, wv0.x, fmaf( v.x, wv0.y, ai[0][2*jp  ]));
                ar[0][2*jp+1] = fmaf(v.z, wv0.x, fmaf(-v.w, wv0.y, ar[0][2*jp+1]));
                ai[0][2*jp+1] = fmaf(v.w, wv0.x, fmaf( v.z, wv0.y, ai[0][2*jp+1]));
                ar[1][2*jp  ] = fmaf(v.x, wv1.x, fmaf(-v.y, wv1.y, ar[1][2*jp  ]));
                ai[1][2*jp  ] = fmaf(v.y, wv1.x, fmaf( v.x, wv1.y, ai[1][2*jp  ]));
                ar[1][2*jp+1] = fmaf(v.z, wv1.x, fmaf(-v.w, wv1.y, ar[1][2*jp+1]));
                ai[1][2*jp+1] = fmaf(v.w, wv1.x, fmaf( v.z, wv1.y, ai[1][2*jp+1]));
            }
        }
        __syncthreads();
    }

    // softshrink epilogue
    #pragma unroll
    for (int oo = 0; oo < 2; oo++) {
        int o = x_ + 48 * oo;
        float2* ob = out + (size_t)k * BS * S_ + (size_t)o * S_;
        #pragma unroll
        for (int j = 0; j < 16; j++) {
            int s = s0 + jb + j;
            if (s < S_) {
                float r = ar[oo][j], m = ai[oo][j];
                r = copysignf(fmaxf(fabsf(r) - LAM, 0.f), r);
                m = copysignf(fmaxf(fabsf(m) - LAM, 0.f), m);
                ob[s] = make_float2(r, m);
            }
        }
    }
}

// ---------------------------------------------------------------------------
// Kernel 6: inverse c2r W DFT as GEMM. Reads g_S2 (inverse-H output).
// Threads (96,2): each owns n in {x, x+96} and 16 rows [16y, 16y+16).
// ---------------------------------------------------------------------------
__global__ __launch_bounds__(192)
void k_inv_w(const float* __restrict__ x, float* __restrict__ out) {
    __shared__ float2 tws[16 * KP];                    // [i][n]
    __shared__ __align__(16) float2 xs[16 * 34];       // [i][row], pad 34
    int r0  = blockIdx.x * 32;
    int x_  = threadIdx.x;           // 0..95
    int y_  = threadIdx.y;           // 0..1
    int tid = x_ + 96 * y_;
    int jb  = y_ * 16;

    float U[2][16], V[2][16];
    #pragma unroll
    for (int oo = 0; oo < 2; oo++)
        #pragma unroll
        for (int j = 0; j < 16; j++) { U[oo][j] = 0.f; V[oo][j] = 0.f; }

    for (int w0 = 0; w0 < 96; w0 += 16) {
        for (int tt = tid; tt < 16 * KP; tt += 192)
            tws[tt] = g_Ti[w0 * KP + tt];
        for (int tt = tid; tt < 16 * 32; tt += 192) {
            int i = tt % 16, j = tt / 16;
            int w = w0 + i;
            float2 v = (w < WK) ? g_S2[(size_t)(r0 + j) * WK + w]
                                : make_float2(0.f, 0.f);
            xs[i * 34 + j] = v;
        }
        __syncthreads();
        #pragma unroll 4
        for (int i = 0; i < 16; i++) {
            float2 wv0 = tws[i * KP + x_];             // (cos, sin)
            float2 wv1 = tws[i * KP + x_ + 96];
            const float4* xp4 = reinterpret_cast<const float4*>(&xs[i * 34 + jb]);
            #pragma unroll
            for (int jp = 0; jp < 8; jp++) {
                float4 v = xp4[jp];                    // Xr0,Xi0,Xr1,Xi1
                U[0][2*jp  ] = fmaf(v.x, wv0.x, U[0][2*jp  ]);
                V[0][2*jp  ] = fmaf(v.y, wv0.y, V[0][2*jp  ]);
                U[0][2*jp+1] = fmaf(v.z, wv0.x, U[0][2*jp+1]);
                V[0][2*jp+1] = fmaf(v.w, wv0.y, V[0][2*jp+1]);
                U[1][2*jp  ] = fmaf(v.x, wv1.x, U[1][2*jp  ]);
                V[1][2*jp  ] = fmaf(v.y, wv1.y, V[1][2*jp  ]);
                U[1][2*jp+1] = fmaf(v.z, wv1.x, U[1][2*jp+1]);
                V[1][2*jp+1] = fmaf(v.w, wv1.y, V[1][2*jp+1]);
            }
        }
        __syncthreads();
    }

    const float k2 = 2.0f * ORTHO;
    #pragma unroll
    for (int oo = 0; oo < 2; oo++) {
        int n = x_ + 96 * oo;
        if (n <= 180) {
            #pragma unroll
            for (int j = 0; j < 16; j++) {
                size_t rb = (size_t)(r0 + jb + j) * W_;
                out[rb + n] = fmaf(k2, U[oo][j] - V[oo][j], x[rb + n]);
                if (n > 0 && n < 180) {
                    int nm = W_ - n;
                    out[rb + nm] = fmaf(k2, U[oo][j] + V[oo][j], x[rb + nm]);
                }
            }
        }
    }
}

// ---------------------------------------------------------------------------
extern "C" void kernel_launch(void* const* d_in, const int* in_sizes, int n_in,
                              void* d_out, int out_size) {
    const float* x  = (const float*)d_in[0];
    const float* w1 = (const float*)d_in[1];
    const float* b1 = (const float*)d_in[2];
    const float* w2 = (const float*)d_in[3];
    const float* b2 = (const float*)d_in[4];
    float* out = (float*)d_out;

    float2* S1; float2* S2;
    cudaGetSymbolAddress((void**)&S1, g_S1);
    cudaGetSymbolAddress((void**)&S2, g_S2);

    const int stiles = (S_ + 63) / 64;             // 256
    const int mix_smem = (32 * 96 + 32 * 64 + 96 * 66) * (int)sizeof(float2);

    cudaFuncSetAttribute(k_mix_f,
                         cudaFuncAttributeMaxDynamicSharedMemorySize, mix_smem);

    // 0. DFT matrices + twiddles
    k_init_T<<<(KP * 96 + 255) / 256, 256>>>();
    // 0b. fold x -> PM[n][row]
    k_fold<<<ROWS / 32, 256>>>(x);
    // 1. forward W DFT as GEMM (PM -> S1), ortho-scaled
    k_fwd_w<<<ROWS / 64, dim3(48, 4)>>>();
    // 2. forward H DFT (S1 -> S2)
    k_fft_h<-1><<<dim3(WK / WT, CH), 224>>>(S1, S2);
    // 3+4. fused mix: relu(w1) then softshrink(w2)  (S2 -> S1)
    k_mix_f<<<dim3(stiles, NB), dim3(48, 4), mix_smem>>>(S2, S1, w1, b1, w2, b2);
    // 5. inverse H DFT (S1 -> S2)
    k_fft_h<+1><<<dim3(WK / WT, CH), 224>>>(S1, S2);
    // 6. inverse W c2r as GEMM + residual (S2, x -> out)
    k_inv_w<<<ROWS / 32, dim3(96, 2)>>>(x, out);
}

// round 12
// speedup vs baseline: 2.6244x; 1.0601x over previous
#include <cuda_runtime.h>
#include <math.h>

// Problem dims
#define CH   768
#define H_   180
#define W_   360
#define WK   91           // kept W modes (rfft bins 0..90; 91..180 provably zero)
#define NB   8
#define BS   96
#define S_   (H_ * WK)    // 16380 spectral points per channel
#define ROWS (CH * H_)    // 138240 spatial rows
#define ORTHO 0.003928371006591931f   // 1/sqrt(180*360)
#define LAM  0.01f

// Scratch buffers
__device__ float2 g_S1[(size_t)CH * S_];
__device__ float2 g_S2[(size_t)CH * S_];

// Precomputed DFT matrices / twiddles (double-folded, K = 96)
__device__ float2 g_Tf[96 * 96];   // fwd:  [n][w] = (cos(t n w), -sin(t n w)); n>90 -> 0
__device__ float2 g_Ti[96 * 96];   // inv:  [w][n] = (cos, sin); w=0 -> (0.5,0); w>90 -> 0
__device__ float2 g_twHf[H_];      // e^{-2pi i n/180}
__device__ float2 g_twHb[H_];      // e^{+2pi i n/180}

__device__ __forceinline__ float2 cmul(float2 a, float2 b) {
    return make_float2(fmaf(a.x, b.x, -a.y * b.y),
                       fmaf(a.x, b.y,  a.y * b.x));
}

// ---------------------------------------------------------------------------
// Init: DFT matrices + H twiddles.
// ---------------------------------------------------------------------------
__global__ void k_init_T() {
    int i = blockIdx.x * 256 + threadIdx.x;
    if (i < 96 * 96) {
        int n = i / 96, w = i % 96;           // g_Tf [n][w]
        float2 vf = make_float2(0.f, 0.f);
        if (n <= 90) {
            float s, c;
            sincospif((float)((n * w) % 360) / 180.0f, &s, &c);
            vf = make_float2(c, -s);
        }
        g_Tf[i] = vf;
        int wi = i / 96, ni = i % 96;         // g_Ti [w][n]
        float2 vi = make_float2(0.f, 0.f);
        if (wi == 0) vi = make_float2(0.5f, 0.f);
        else if (wi <= 90) {
            float s, c;
            sincospif((float)((ni * wi) % 360) / 180.0f, &s, &c);
            vi = make_float2(c, s);
        }
        g_Ti[i] = vi;
    }
    if (i < H_) {
        float s, c;
        sincospif((float)i / 90.0f, &s, &c);
        g_twHf[i] = make_float2(c, -s);
        g_twHb[i] = make_float2(c,  s);
    }
}

// ---------------------------------------------------------------------------
// Kernel 1: forward W r2c DFT, double-folded (K=96), fold fused into staging.
// Even bins w use (pe,me); odd bins use (po,mo):
//   pe[0]=x0+x180, po[0]=x0-x180; pe[90]=po[90]=x90+x270, me[90]=mo[90]=x90-x270
//   n=1..89: p=x[n]+x[360-n], m=x[n]-x[360-n], q=x[180-n]+x[180+n],
//            mq=x[180-n]-x[180+n]; pe=p+q, po=p-q, me=m-mq, mo=m+mq
// re = sum pe/po * cos, im = sum me/mo * (-sin).
// Threads (48,4): bins {x, x+48} (same parity), 16 rows each. Dynamic smem.
// ---------------------------------------------------------------------------
__global__ __launch_bounds__(192)
void k_fwd_w(const float* __restrict__ x) {
    extern __shared__ float2 smf[];
    float2* tws = smf;                 // 32*96
    float2* asE = smf + 32 * 96;       // 32*66
    float2* asO = smf + 32 * 96 + 32 * 66;
    int r0  = blockIdx.x * 64;
    int x_  = threadIdx.x;             // 0..47
    int y_  = threadIdx.y;             // 0..3
    int tid = x_ + 48 * y_;

    float re[2][16], im[2][16];
    #pragma unroll
    for (int oo = 0; oo < 2; oo++)
        #pragma unroll
        for (int j = 0; j < 16; j++) { re[oo][j] = 0.f; im[oo][j] = 0.f; }

    const float2* ab = (x_ & 1) ? asO : asE;

    for (int nc = 0; nc < 96; nc += 32) {
        for (int t = tid; t < 32 * 96; t += 192)
            tws[t] = g_Tf[nc * 96 + t];
        for (int t = tid; t < 32 * 64; t += 192) {
            int i = t & 31, j = t >> 5;
            int n = nc + i;
            const float* xr = x + (size_t)(r0 + j) * W_;
            float pe = 0.f, po = 0.f, me = 0.f, mo = 0.f;
            if (n == 0) {
                float a = xr[0], d = xr[180];
                pe = a + d; po = a - d;
            } else if (n < 90) {
                float a = xr[n], b = xr[W_ - n];
                float c = xr[180 - n], d = xr[180 + n];
                float p = a + b, m = a - b, q = c + d, mq = c - d;
                pe = p + q; po = p - q; me = m - mq; mo = m + mq;
            } else if (n == 90) {
                float a = xr[90], b = xr[270];
                pe = a + b; po = pe; me = a - b; mo = me;
            }
            asE[i * 66 + j] = make_float2(pe, me);
            asO[i * 66 + j] = make_float2(po, mo);
        }
        __syncthreads();
        #pragma unroll 4
        for (int i = 0; i < 32; i++) {
            float2 wv0 = tws[i * 96 + x_];             // (cos, -sin)
            float2 wv1 = tws[i * 96 + x_ + 48];
            const float4* ap = reinterpret_cast<const float4*>(ab + i * 66 + y_ * 16);
            #pragma unroll
            for (int jp = 0; jp < 8; jp++) {
                float4 v = ap[jp];                     // a0,b0,a1,b1 (2 rows)
                re[0][2*jp  ] = fmaf(v.x, wv0.x, re[0][2*jp  ]);
                im[0][2*jp  ] = fmaf(v.y, wv0.y, im[0][2*jp  ]);
                re[0][2*jp+1] = fmaf(v.z, wv0.x, re[0][2*jp+1]);
                im[0][2*jp+1] = fmaf(v.w, wv0.y, im[0][2*jp+1]);
                re[1][2*jp  ] = fmaf(v.x, wv1.x, re[1][2*jp  ]);
                im[1][2*jp  ] = fmaf(v.y, wv1.y, im[1][2*jp  ]);
                re[1][2*jp+1] = fmaf(v.z, wv1.x, re[1][2*jp+1]);
                im[1][2*jp+1] = fmaf(v.w, wv1.y, im[1][2*jp+1]);
            }
        }
        __syncthreads();
    }
    #pragma unroll
    for (int oo = 0; oo < 2; oo++) {
        int o = x_ + 48 * oo;
        if (o < WK) {
            #pragma unroll
            for (int j = 0; j < 16; j++) {
                int row = r0 + y_ * 16 + j;
                g_S1[(size_t)row * WK + o] =
                    make_float2(re[oo][j] * ORTHO, im[oo][j] * ORTHO);
            }
        }
    }
}

// ---------------------------------------------------------------------------
// Kernels 2/5: 180-pt complex DFT along H, radix-4 sharing + 3-way k-blocking.
// (unchanged from R11 passing version)
// ---------------------------------------------------------------------------
#define WT 13
template <int SGN>
__global__ __launch_bounds__(224)
void k_fft_h(const float2* __restrict__ in, float2* __restrict__ out) {
    __shared__ float2 tile[H_ * WT];
    __shared__ float2 tw[H_];
    int c  = blockIdx.y;
    int w0 = blockIdx.x * WT;
    const float2* base = in + (size_t)c * S_;
    for (int i = threadIdx.x; i < H_ * WT; i += 224) {
        int h = i / WT, wl = i % WT;
        tile[i] = base[(size_t)h * WK + w0 + wl];
    }
    const float2* gt = (SGN < 0) ? g_twHf : g_twHb;
    for (int n = threadIdx.x; n < H_; n += 224) tw[n] = gt[n];
    __syncthreads();

    int tid = threadIdx.x;
    if (tid < 195) {
        int k0 = tid / WT, wl = tid % WT;    // k0 in [0,15)
        float2 w60  = tw[60];                // omega   = W^60
        float2 w120 = tw[120];               // omega^2 = W^120
        int s4 = 4 * k0;                     // <= 56

        float2 A[3][4];
        #pragma unroll
        for (int t = 0; t < 3; t++)
            #pragma unroll
            for (int j = 0; j < 4; j++) A[t][j] = make_float2(0.f, 0.f);

        int idx = 0;
        #pragma unroll 3
        for (int q = 0; q < 15; q++) {
            #pragma unroll
            for (int u = 0; u < 3; u++) {
                int r = 3 * q + u;
                float2 e0 = tw[idx];
                float2 e1, e2;
                if (u == 0)      { e1 = e0; e2 = e0; }
                else if (u == 1) { e1 = cmul(e0, w60);  e2 = cmul(e0, w120); }
                else             { e1 = cmul(e0, w120); e2 = cmul(e0, w60);  }
                float2 z0 = tile[(4 * r + 0) * WT + wl];
                float2 z1 = tile[(4 * r + 1) * WT + wl];
                float2 z2 = tile[(4 * r + 2) * WT + wl];
                float2 z3 = tile[(4 * r + 3) * WT + wl];
                #pragma unroll
                for (int t = 0; t < 3; t++) {
                    float2 e = (t == 0) ? e0 : (t == 1) ? e1 : e2;
                    A[t][0].x = fmaf(z0.x, e.x, fmaf(-z0.y, e.y, A[t][0].x));
                    A[t][0].y = fmaf(z0.x, e.y, fmaf( z0.y, e.x, A[t][0].y));
                    A[t][1].x = fmaf(z1.x, e.x, fmaf(-z1.y, e.y, A[t][1].x));
                    A[t][1].y = fmaf(z1.x, e.y, fmaf( z1.y, e.x, A[t][1].y));
                    A[t][2].x = fmaf(z2.x, e.x, fmaf(-z2.y, e.y, A[t][2].x));
                    A[t][2].y = fmaf(z2.x, e.y, fmaf( z2.y, e.x, A[t][2].y));
                    A[t][3].x = fmaf(z3.x, e.x, fmaf(-z3.y, e.y, A[t][3].x));
                    A[t][3].y = fmaf(z3.x, e.y, fmaf( z3.y, e.x, A[t][3].y));
                }
                idx += s4; if (idx >= H_) idx -= H_;
            }
        }

        float2* ob = out + (size_t)c * S_;
        #pragma unroll
        for (int t = 0; t < 3; t++) {
            int kt = k0 + 15 * t;
            float2 PP = A[t][0], QP = A[t][1], PQ = A[t][2], QQ = A[t][3];
            float2 w1t = tw[kt];
            float2 w2t = tw[2 * kt];
            float2 t2  = cmul(w2t, PQ);
            float2 t2q = cmul(w2t, QQ);
            float2 Pp = make_float2(PP.x + t2.x,  PP.y + t2.y);
            float2 Pm = make_float2(PP.x - t2.x,  PP.y - t2.y);
            float2 Qp = make_float2(QP.x + t2q.x, QP.y + t2q.y);
            float2 Qm = make_float2(QP.x - t2q.x, QP.y - t2q.y);
            float2 up = cmul(w1t, Qp);
            float2 um = cmul(w1t, Qm);
            float2 iu = make_float2((float)(-SGN) * um.y, (float)SGN * um.x);
            size_t o0 = (size_t)kt * WK + w0 + wl;
            ob[o0           ] = make_float2(Pp.x + up.x, Pp.y + up.y);
            ob[o0 +  45 * WK] = make_float2(Pm.x + iu.x, Pm.y + iu.y);
            ob[o0 +  90 * WK] = make_float2(Pp.x - up.x, Pp.y - up.y);
            ob[o0 + 135 * WK] = make_float2(Pm.x - iu.x, Pm.y - iu.y);
        }
    }
}

// ---------------------------------------------------------------------------
// Kernels 3+4 fused: o2 = softshrink(w2 @ relu(w1 @ in + b1) + b2).
// (unchanged from R11 passing version)
// ---------------------------------------------------------------------------
__global__ __launch_bounds__(192)
void k_mix_f(const float2* __restrict__ in, float2* __restrict__ out,
             const float* __restrict__ w1_, const float* __restrict__ b1_,
             const float* __restrict__ w2_, const float* __restrict__ b2_) {
    const int TS = 64;
    extern __shared__ float2 sm[];
    float2* ws  = sm;                        // 32*96
    float2* as  = sm + 32 * 96;              // 32*64
    float2* o1s = sm + 32 * 96 + 32 * TS;    // 96*66
    int k   = blockIdx.y;
    int s0  = blockIdx.x * TS;
    int x_  = threadIdx.x;           // 0..47
    int y_  = threadIdx.y;           // 0..3
    int tid = x_ + 48 * y_;
    int jb  = y_ * 16;

    float ar[2][16], ai[2][16];
    {
        const float2* bb = (const float2*)b1_;
        float2 bv0 = bb[k * BS + x_];
        float2 bv1 = bb[k * BS + x_ + 48];
        #pragma unroll
        for (int j = 0; j < 16; j++) {
            ar[0][j] = bv0.x; ai[0][j] = bv0.y;
            ar[1][j] = bv1.x; ai[1][j] = bv1.y;
        }
    }

    const float2* inb = in + (size_t)k * BS * S_;
    const float2* wb1 = (const float2*)w1_ + (size_t)k * BS * BS;

    for (int ic = 0; ic < BS; ic += 32) {
        for (int t = tid; t < 32 * BS; t += 192)
            ws[t] = wb1[(size_t)ic * BS + t];
        for (int t = tid; t < 32 * TS; t += 192) {
            int i = t / TS, sl = t % TS;
            int s = s0 + sl;
            as[t] = (s < S_) ? inb[(size_t)(ic + i) * S_ + s]
                             : make_float2(0.f, 0.f);
        }
        __syncthreads();
        #pragma unroll 4
        for (int i = 0; i < 32; i++) {
            float2 wv0 = ws[i * BS + x_];
            float2 wv1 = ws[i * BS + x_ + 48];
            const float4* ap = reinterpret_cast<const float4*>(&as[i * TS + jb]);
            #pragma unroll
            for (int jp = 0; jp < 8; jp++) {
                float4 v = ap[jp];                     // r0,i0,r1,i1
                ar[0][2*jp  ] = fmaf(v.x, wv0.x, fmaf(-v.y, wv0.y, ar[0][2*jp  ]));
                ai[0][2*jp  ] = fmaf(v.y, wv0.x, fmaf( v.x, wv0.y, ai[0][2*jp  ]));
                ar[0][2*jp+1] = fmaf(v.z, wv0.x, fmaf(-v.w, wv0.y, ar[0][2*jp+1]));
                ai[0][2*jp+1] = fmaf(v.w, wv0.x, fmaf( v.z, wv0.y, ai[0][2*jp+1]));
                ar[1][2*jp  ] = fmaf(v.x, wv1.x, fmaf(-v.y, wv1.y, ar[1][2*jp  ]));
                ai[1][2*jp  ] = fmaf(v.y, wv1.x, fmaf( v.x, wv1.y, ai[1][2*jp  ]));
                ar[1][2*jp+1] = fmaf(v.z, wv1.x, fmaf(-v.w, wv1.y, ar[1][2*jp+1]));
                ai[1][2*jp+1] = fmaf(v.w, wv1.x, fmaf( v.z, wv1.y, ai[1][2*jp+1]));
            }
        }
        __syncthreads();
    }

    #pragma unroll
    for (int oo = 0; oo < 2; oo++) {
        int o = x_ + 48 * oo;
        #pragma unroll
        for (int j = 0; j < 16; j++)
            o1s[o * 66 + jb + j] =
                make_float2(fmaxf(ar[oo][j], 0.f), fmaxf(ai[oo][j], 0.f));
    }
    {
        const float2* bb = (const float2*)b2_;
        float2 bv0 = bb[k * BS + x_];
        float2 bv1 = bb[k * BS + x_ + 48];
        #pragma unroll
        for (int j = 0; j < 16; j++) {
            ar[0][j] = bv0.x; ai[0][j] = bv0.y;
            ar[1][j] = bv1.x; ai[1][j] = bv1.y;
        }
    }
    __syncthreads();

    const float2* wb2 = (const float2*)w2_ + (size_t)k * BS * BS;
    for (int ic = 0; ic < BS; ic += 32) {
        for (int t = tid; t < 32 * BS; t += 192)
            ws[t] = wb2[(size_t)ic * BS + t];
        __syncthreads();
        #pragma unroll 4
        for (int i = 0; i < 32; i++) {
            float2 wv0 = ws[i * BS + x_];
            float2 wv1 = ws[i * BS + x_ + 48];
            const float4* ap =
                reinterpret_cast<const float4*>(&o1s[(ic + i) * 66 + jb]);
            #pragma unroll
            for (int jp = 0; jp < 8; jp++) {
                float4 v = ap[jp];
                ar[0][2*jp  ] = fmaf(v.x, wv0.x, fmaf(-v.y, wv0.y, ar[0][2*jp  ]));
                ai[0][2*jp  ] = fmaf(v.y, wv0.x, fmaf( v.x, wv0.y, ai[0][2*jp  ]));
                ar[0][2*jp+1] = fmaf(v.z, wv0.x, fmaf(-v.w, wv0.y, ar[0][2*jp+1]));
                ai[0][2*jp+1] = fmaf(v.w, wv0.x, fmaf( v.z, wv0.y, ai[0][2*jp+1]));
                ar[1][2*jp  ] = fmaf(v.x, wv1.x, fmaf(-v.y, wv1.y, ar[1][2*jp  ]));
                ai[1][2*jp  ] = fmaf(v.y, wv1.x, fmaf( v.x, wv1.y, ai[1][2*jp  ]));
                ar[1][2*jp+1] = fmaf(v.z, wv1.x, fmaf(-v.w, wv1.y, ar[1][2*jp+1]));
                ai[1][2*jp+1] = fmaf(v.w, wv1.x, fmaf( v.z, wv1.y, ai[1][2*jp+1]));
            }
        }
        __syncthreads();
    }

    #pragma unroll
    for (int oo = 0; oo < 2; oo++) {
        int o = x_ + 48 * oo;
        float2* ob = out + (size_t)k * BS * S_ + (size_t)o * S_;
        #pragma unroll
        for (int j = 0; j < 16; j++) {
            int s = s0 + jb + j;
            if (s < S_) {
                float r = ar[oo][j], m = ai[oo][j];
                r = copysignf(fmaxf(fabsf(r) - LAM, 0.f), r);
                m = copysignf(fmaxf(fabsf(m) - LAM, 0.f), m);
                ob[s] = make_float2(r, m);
            }
        }
    }
}

// ---------------------------------------------------------------------------
// Kernel 6: inverse c2r W DFT, parity-split partial sums (K halved).
// Ue/Uo = sum_{even/odd w} Xr cos(tnw) (w=0 col holds 0.5), Ve/Vo = sum Xi sin.
//   out[n]      = k2(Ue+Uo-Ve-Vo)+x ; out[360-n] = k2(Ue+Uo+Ve+Vo)+x
//   out[180-n]  = k2(Ue-Uo+Ve-Vo)+x ; out[180+n] = k2(Ue-Uo-Ve+Vo)+x
// Threads (48,4): n in {x, x+48} (valid n<=90), 8 rows each; 32 rows/block.
// ---------------------------------------------------------------------------
__global__ __launch_bounds__(192)
void k_inv_w(const float* __restrict__ x, float* __restrict__ out) {
    __shared__ float2 tws[16 * 96];                    // [i][n]
    __shared__ __align__(16) float2 xs[16 * 34];       // [i][row], pad 34
    int r0  = blockIdx.x * 32;
    int x_  = threadIdx.x;           // 0..47
    int y_  = threadIdx.y;           // 0..3
    int tid = x_ + 48 * y_;
    int jb  = y_ * 8;

    float Ue[2][8], Uo[2][8], Ve[2][8], Vo[2][8];
    #pragma unroll
    for (int b = 0; b < 2; b++)
        #pragma unroll
        for (int j = 0; j < 8; j++) {
            Ue[b][j] = 0.f; Uo[b][j] = 0.f; Ve[b][j] = 0.f; Vo[b][j] = 0.f;
        }

    for (int w0 = 0; w0 < 96; w0 += 16) {
        for (int tt = tid; tt < 16 * 96; tt += 192)
            tws[tt] = g_Ti[w0 * 96 + tt];
        for (int tt = tid; tt < 16 * 32; tt += 192) {
            int i = tt & 15, j = tt >> 4;
            int w = w0 + i;
            float2 v = (w < WK) ? g_S2[(size_t)(r0 + j) * WK + w]
                                : make_float2(0.f, 0.f);
            xs[i * 34 + j] = v;
        }
        __syncthreads();
        #pragma unroll
        for (int i2 = 0; i2 < 8; i2++) {
            {   // even w
                int i = 2 * i2;
                float2 wv0 = tws[i * 96 + x_];         // (cos, sin)
                float2 wv1 = tws[i * 96 + x_ + 48];
                const float4* ap = reinterpret_cast<const float4*>(&xs[i * 34 + jb]);
                #pragma unroll
                for (int jp = 0; jp < 4; jp++) {
                    float4 v = ap[jp];                 // Xr0,Xi0,Xr1,Xi1
                    Ue[0][2*jp  ] = fmaf(v.x, wv0.x, Ue[0][2*jp  ]);
                    Ve[0][2*jp  ] = fmaf(v.y, wv0.y, Ve[0][2*jp  ]);
                    Ue[0][2*jp+1] = fmaf(v.z, wv0.x, Ue[0][2*jp+1]);
                    Ve[0][2*jp+1] = fmaf(v.w, wv0.y, Ve[0][2*jp+1]);
                    Ue[1][2*jp  ] = fmaf(v.x, wv1.x, Ue[1][2*jp  ]);
                    Ve[1][2*jp  ] = fmaf(v.y, wv1.y, Ve[1][2*jp  ]);
                    Ue[1][2*jp+1] = fmaf(v.z, wv1.x, Ue[1][2*jp+1]);
                    Ve[1][2*jp+1] = fmaf(v.w, wv1.y, Ve[1][2*jp+1]);
                }
            }
            {   // odd w
                int i = 2 * i2 + 1;
                float2 wv0 = tws[i * 96 + x_];
                float2 wv1 = tws[i * 96 + x_ + 48];
                const float4* ap = reinterpret_cast<const float4*>(&xs[i * 34 + jb]);
                #pragma unroll
                for (int jp = 0; jp < 4; jp++) {
                    float4 v = ap[jp];
                    Uo[0][2*jp  ] = fmaf(v.x, wv0.x, Uo[0][2*jp  ]);
                    Vo[0][2*jp  ] = fmaf(v.y, wv0.y, Vo[0][2*jp  ]);
                    Uo[0][2*jp+1] = fmaf(v.z, wv0.x, Uo[0][2*jp+1]);
                    Vo[0][2*jp+1] = fmaf(v.w, wv0.y, Vo[0][2*jp+1]);
                    Uo[1][2*jp  ] = fmaf(v.x, wv1.x, Uo[1][2*jp  ]);
                    Vo[1][2*jp  ] = fmaf(v.y, wv1.y, Vo[1][2*jp  ]);
                    Uo[1][2*jp+1] = fmaf(v.z, wv1.x, Uo[1][2*jp+1]);
                    Vo[1][2*jp+1] = fmaf(v.w, wv1.y, Vo[1][2*jp+1]);
                }
            }
        }
        __syncthreads();
    }

    const float k2 = 2.0f * ORTHO;
    #pragma unroll
    for (int b = 0; b < 2; b++) {
        int n = x_ + 48 * b;
        if (n <= 90) {
            #pragma unroll
            for (int j = 0; j < 8; j++) {
                size_t rb = (size_t)(r0 + jb + j) * W_;
                float ue = Ue[b][j], uo = Uo[b][j];
                float ve = Ve[b][j], vo = Vo[b][j];
                out[rb + n] = fmaf(k2, ue + uo - ve - vo, x[rb + n]);
                if (n >= 1)
                    out[rb + W_ - n] = fmaf(k2, ue + uo + ve + vo, x[rb + W_ - n]);
                if (n >= 1 && n <= 89) {
                    out[rb + 180 - n] = fmaf(k2, ue - uo + ve - vo, x[rb + 180 - n]);
                    out[rb + 180 + n] = fmaf(k2, ue - uo - ve + vo, x[rb + 180 + n]);
                }
                if (n == 0)
                    out[rb + 180] = fmaf(k2, ue - uo, x[rb + 180]);
            }
        }
    }
}

// ---------------------------------------------------------------------------
extern "C" void kernel_launch(void* const* d_in, const int* in_sizes, int n_in,
                              void* d_out, int out_size) {
    const float* x  = (const float*)d_in[0];
    const float* w1 = (const float*)d_in[1];
    const float* b1 = (const float*)d_in[2];
    const float* w2 = (const float*)d_in[3];
    const float* b2 = (const float*)d_in[4];
    float* out = (float*)d_out;

    float2* S1; float2* S2;
    cudaGetSymbolAddress((void**)&S1, g_S1);
    cudaGetSymbolAddress((void**)&S2, g_S2);

    const int stiles   = (S_ + 63) / 64;           // 256
    const int mix_smem = (32 * 96 + 32 * 64 + 96 * 66) * (int)sizeof(float2);
    const int fwd_smem = (32 * 96 + 2 * 32 * 66) * (int)sizeof(float2);

    cudaFuncSetAttribute(k_mix_f,
                         cudaFuncAttributeMaxDynamicSharedMemorySize, mix_smem);
    cudaFuncSetAttribute(k_fwd_w,
                         cudaFuncAttributeMaxDynamicSharedMemorySize, fwd_smem);

    // 0. DFT matrices + twiddles
    k_init_T<<<(96 * 96 + 255) / 256, 256>>>();
    // 1. forward W DFT (fold fused; x -> S1), ortho-scaled
    k_fwd_w<<<ROWS / 64, dim3(48, 4), fwd_smem>>>(x);
    // 2. forward H DFT (S1 -> S2)
    k_fft_h<-1><<<dim3(WK / WT, CH), 224>>>(S1, S2);
    // 3+4. fused mix: relu(w1) then softshrink(w2)  (S2 -> S1)
    k_mix_f<<<dim3(stiles, NB), dim3(48, 4), mix_smem>>>(S2, S1, w1, b1, w2, b2);
    // 5. inverse H DFT (S1 -> S2)
    k_fft_h<+1><<<dim3(WK / WT, CH), 224>>>(S1, S2);
    // 6. inverse W c2r (parity-split) + residual (S2, x -> out)
    k_inv_w<<<ROWS / 32, dim3(48, 4)>>>(x, out);
}

// round 13
// speedup vs baseline: 3.2796x; 1.2496x over previous
#include <cuda_runtime.h>
#include <math.h>
#include <stdint.h>

// Problem dims
#define CH   768
#define H_   180
#define W_   360
#define WK   91           // kept W modes (rfft bins 0..90; 91..180 provably zero)
#define NB   8
#define BS   96
#define S_   (H_ * WK)    // 16380 spectral points per channel
#define ROWS (CH * H_)    // 138240 spatial rows
#define ORTHO 0.003928371006591931f   // 1/sqrt(180*360)
#define LAM  0.01f

// Scratch buffers
__device__ float2 g_S1[(size_t)CH * S_];
__device__ float2 g_S2[(size_t)CH * S_];

// Precomputed DFT matrices / twiddles (double-folded, K = 96)
__device__ float2 g_Tf[96 * 96];   // fwd:  [n][w] = (cos(t n w), -sin(t n w)); n>90 -> 0
__device__ float2 g_Ti[96 * 96];   // inv:  [w][n] = (cos, sin); w=0 -> (0.5,0); w>90 -> 0
__device__ float2 g_twHf[H_];      // e^{-2pi i n/180}
__device__ float2 g_twHb[H_];      // e^{+2pi i n/180}

__device__ __forceinline__ float2 cmul(float2 a, float2 b) {
    return make_float2(fmaf(a.x, b.x, -a.y * b.y),
                       fmaf(a.x, b.y,  a.y * b.x));
}

__device__ __forceinline__ uint32_t f2tf(float f) {
    uint32_t u;
    asm("cvt.rna.tf32.f32 %0, %1;" : "=r"(u) : "f"(f));
    return u;
}

__device__ __forceinline__ void mma_tf32(float* d,
    uint32_t a0, uint32_t a1, uint32_t a2, uint32_t a3,
    uint32_t b0, uint32_t b1) {
    asm volatile(
        "mma.sync.aligned.m16n8k8.row.col.f32.tf32.tf32.f32 "
        "{%0,%1,%2,%3}, {%4,%5,%6,%7}, {%8,%9}, {%0,%1,%2,%3};"
        : "+f"(d[0]), "+f"(d[1]), "+f"(d[2]), "+f"(d[3])
        : "r"(a0), "r"(a1), "r"(a2), "r"(a3), "r"(b0), "r"(b1));
}

// ---------------------------------------------------------------------------
// Init: DFT matrices + H twiddles.
// ---------------------------------------------------------------------------
__global__ void k_init_T() {
    int i = blockIdx.x * 256 + threadIdx.x;
    if (i < 96 * 96) {
        int n = i / 96, w = i % 96;           // g_Tf [n][w]
        float2 vf = make_float2(0.f, 0.f);
        if (n <= 90) {
            float s, c;
            sincospif((float)((n * w) % 360) / 180.0f, &s, &c);
            vf = make_float2(c, -s);
        }
        g_Tf[i] = vf;
        int wi = i / 96, ni = i % 96;         // g_Ti [w][n]
        float2 vi = make_float2(0.f, 0.f);
        if (wi == 0) vi = make_float2(0.5f, 0.f);
        else if (wi <= 90) {
            float s, c;
            sincospif((float)((ni * wi) % 360) / 180.0f, &s, &c);
            vi = make_float2(c, s);
        }
        g_Ti[i] = vi;
    }
    if (i < H_) {
        float s, c;
        sincospif((float)i / 90.0f, &s, &c);
        g_twHf[i] = make_float2(c, -s);
        g_twHb[i] = make_float2(c,  s);
    }
}

// ---------------------------------------------------------------------------
// Kernel 1: forward W r2c DFT, double-folded (K=96), fold fused into staging.
// (unchanged from R12 passing version)
// ---------------------------------------------------------------------------
__global__ __launch_bounds__(192)
void k_fwd_w(const float* __restrict__ x) {
    extern __shared__ float2 smf[];
    float2* tws = smf;                 // 32*96
    float2* asE = smf + 32 * 96;       // 32*66
    float2* asO = smf + 32 * 96 + 32 * 66;
    int r0  = blockIdx.x * 64;
    int x_  = threadIdx.x;             // 0..47
    int y_  = threadIdx.y;             // 0..3
    int tid = x_ + 48 * y_;

    float re[2][16], im[2][16];
    #pragma unroll
    for (int oo = 0; oo < 2; oo++)
        #pragma unroll
        for (int j = 0; j < 16; j++) { re[oo][j] = 0.f; im[oo][j] = 0.f; }

    const float2* ab = (x_ & 1) ? asO : asE;

    for (int nc = 0; nc < 96; nc += 32) {
        for (int t = tid; t < 32 * 96; t += 192)
            tws[t] = g_Tf[nc * 96 + t];
        for (int t = tid; t < 32 * 64; t += 192) {
            int i = t & 31, j = t >> 5;
            int n = nc + i;
            const float* xr = x + (size_t)(r0 + j) * W_;
            float pe = 0.f, po = 0.f, me = 0.f, mo = 0.f;
            if (n == 0) {
                float a = xr[0], d = xr[180];
                pe = a + d; po = a - d;
            } else if (n < 90) {
                float a = xr[n], b = xr[W_ - n];
                float c = xr[180 - n], d = xr[180 + n];
                float p = a + b, m = a - b, q = c + d, mq = c - d;
                pe = p + q; po = p - q; me = m - mq; mo = m + mq;
            } else if (n == 90) {
                float a = xr[90], b = xr[270];
                pe = a + b; po = pe; me = a - b; mo = me;
            }
            asE[i * 66 + j] = make_float2(pe, me);
            asO[i * 66 + j] = make_float2(po, mo);
        }
        __syncthreads();
        #pragma unroll 4
        for (int i = 0; i < 32; i++) {
            float2 wv0 = tws[i * 96 + x_];             // (cos, -sin)
            float2 wv1 = tws[i * 96 + x_ + 48];
            const float4* ap = reinterpret_cast<const float4*>(ab + i * 66 + y_ * 16);
            #pragma unroll
            for (int jp = 0; jp < 8; jp++) {
                float4 v = ap[jp];
                re[0][2*jp  ] = fmaf(v.x, wv0.x, re[0][2*jp  ]);
                im[0][2*jp  ] = fmaf(v.y, wv0.y, im[0][2*jp  ]);
                re[0][2*jp+1] = fmaf(v.z, wv0.x, re[0][2*jp+1]);
                im[0][2*jp+1] = fmaf(v.w, wv0.y, im[0][2*jp+1]);
                re[1][2*jp  ] = fmaf(v.x, wv1.x, re[1][2*jp  ]);
                im[1][2*jp  ] = fmaf(v.y, wv1.y, im[1][2*jp  ]);
                re[1][2*jp+1] = fmaf(v.z, wv1.x, re[1][2*jp+1]);
                im[1][2*jp+1] = fmaf(v.w, wv1.y, im[1][2*jp+1]);
            }
        }
        __syncthreads();
    }
    #pragma unroll
    for (int oo = 0; oo < 2; oo++) {
        int o = x_ + 48 * oo;
        if (o < WK) {
            #pragma unroll
            for (int j = 0; j < 16; j++) {
                int row = r0 + y_ * 16 + j;
                g_S1[(size_t)row * WK + o] =
                    make_float2(re[oo][j] * ORTHO, im[oo][j] * ORTHO);
            }
        }
    }
}

// ---------------------------------------------------------------------------
// Kernels 2/5: 180-pt complex DFT along H, radix-4 sharing + 3-way k-blocking.
// (unchanged)
// ---------------------------------------------------------------------------
#define WT 13
template <int SGN>
__global__ __launch_bounds__(224)
void k_fft_h(const float2* __restrict__ in, float2* __restrict__ out) {
    __shared__ float2 tile[H_ * WT];
    __shared__ float2 tw[H_];
    int c  = blockIdx.y;
    int w0 = blockIdx.x * WT;
    const float2* base = in + (size_t)c * S_;
    for (int i = threadIdx.x; i < H_ * WT; i += 224) {
        int h = i / WT, wl = i % WT;
        tile[i] = base[(size_t)h * WK + w0 + wl];
    }
    const float2* gt = (SGN < 0) ? g_twHf : g_twHb;
    for (int n = threadIdx.x; n < H_; n += 224) tw[n] = gt[n];
    __syncthreads();

    int tid = threadIdx.x;
    if (tid < 195) {
        int k0 = tid / WT, wl = tid % WT;    // k0 in [0,15)
        float2 w60  = tw[60];
        float2 w120 = tw[120];
        int s4 = 4 * k0;

        float2 A[3][4];
        #pragma unroll
        for (int t = 0; t < 3; t++)
            #pragma unroll
            for (int j = 0; j < 4; j++) A[t][j] = make_float2(0.f, 0.f);

        int idx = 0;
        #pragma unroll 3
        for (int q = 0; q < 15; q++) {
            #pragma unroll
            for (int u = 0; u < 3; u++) {
                int r = 3 * q + u;
                float2 e0 = tw[idx];
                float2 e1, e2;
                if (u == 0)      { e1 = e0; e2 = e0; }
                else if (u == 1) { e1 = cmul(e0, w60);  e2 = cmul(e0, w120); }
                else             { e1 = cmul(e0, w120); e2 = cmul(e0, w60);  }
                float2 z0 = tile[(4 * r + 0) * WT + wl];
                float2 z1 = tile[(4 * r + 1) * WT + wl];
                float2 z2 = tile[(4 * r + 2) * WT + wl];
                float2 z3 = tile[(4 * r + 3) * WT + wl];
                #pragma unroll
                for (int t = 0; t < 3; t++) {
                    float2 e = (t == 0) ? e0 : (t == 1) ? e1 : e2;
                    A[t][0].x = fmaf(z0.x, e.x, fmaf(-z0.y, e.y, A[t][0].x));
                    A[t][0].y = fmaf(z0.x, e.y, fmaf( z0.y, e.x, A[t][0].y));
                    A[t][1].x = fmaf(z1.x, e.x, fmaf(-z1.y, e.y, A[t][1].x));
                    A[t][1].y = fmaf(z1.x, e.y, fmaf( z1.y, e.x, A[t][1].y));
                    A[t][2].x = fmaf(z2.x, e.x, fmaf(-z2.y, e.y, A[t][2].x));
                    A[t][2].y = fmaf(z2.x, e.y, fmaf( z2.y, e.x, A[t][2].y));
                    A[t][3].x = fmaf(z3.x, e.x, fmaf(-z3.y, e.y, A[t][3].x));
                    A[t][3].y = fmaf(z3.x, e.y, fmaf( z3.y, e.x, A[t][3].y));
                }
                idx += s4; if (idx >= H_) idx -= H_;
            }
        }

        float2* ob = out + (size_t)c * S_;
        #pragma unroll
        for (int t = 0; t < 3; t++) {
            int kt = k0 + 15 * t;
            float2 PP = A[t][0], QP = A[t][1], PQ = A[t][2], QQ = A[t][3];
            float2 w1t = tw[kt];
            float2 w2t = tw[2 * kt];
            float2 t2  = cmul(w2t, PQ);
            float2 t2q = cmul(w2t, QQ);
            float2 Pp = make_float2(PP.x + t2.x,  PP.y + t2.y);
            float2 Pm = make_float2(PP.x - t2.x,  PP.y - t2.y);
            float2 Qp = make_float2(QP.x + t2q.x, QP.y + t2q.y);
            float2 Qm = make_float2(QP.x - t2q.x, QP.y - t2q.y);
            float2 up = cmul(w1t, Qp);
            float2 um = cmul(w1t, Qm);
            float2 iu = make_float2((float)(-SGN) * um.y, (float)SGN * um.x);
            size_t o0 = (size_t)kt * WK + w0 + wl;
            ob[o0           ] = make_float2(Pp.x + up.x, Pp.y + up.y);
            ob[o0 +  45 * WK] = make_float2(Pm.x + iu.x, Pm.y + iu.y);
            ob[o0 +  90 * WK] = make_float2(Pp.x - up.x, Pp.y - up.y);
            ob[o0 + 135 * WK] = make_float2(Pm.x - iu.x, Pm.y - iu.y);
        }
    }
}

// ---------------------------------------------------------------------------
// Kernels 3+4 fused on TENSOR CORES (tf32 mma.m16n8k8):
// o2 = softshrink(w2 @ relu(w1 @ in + b1) + b2), complex via 4 real mmas.
// 192 threads = 6 warps; warp w owns output rows [16w,16w+16), 64 spatial.
// All smem operands stored as tf32 bits. Pads: weights 104 (bank q+8r),
// data/o1 72 (bank q+8r).
// ---------------------------------------------------------------------------
#define PW 104
#define PA 72
#define MIX_SMEM_WORDS (2*32*PW + 2*32*PA + 2*96*PA)

__global__ __launch_bounds__(192)
void k_mix_f(const float2* __restrict__ in, float2* __restrict__ out,
             const float* __restrict__ w1_, const float* __restrict__ b1_,
             const float* __restrict__ w2_, const float* __restrict__ b2_) {
    extern __shared__ uint32_t smu[];
    uint32_t* WSR = smu;                       // 32*PW
    uint32_t* WSI = WSR + 32 * PW;
    uint32_t* ASR = WSI + 32 * PW;             // 32*PA
    uint32_t* ASI = ASR + 32 * PA;
    uint32_t* O1R = ASI + 32 * PA;             // 96*PA
    uint32_t* O1I = O1R + 96 * PA;

    int k   = blockIdx.y;
    int s0  = blockIdx.x * 64;
    int tid = threadIdx.x;
    int wrp = tid >> 5;
    int lane = tid & 31;
    int q = lane >> 2;           // 0..7
    int r = lane & 3;            // 0..3
    int ob = wrp * 16;

    float Or[8][4], Oi[8][4];

    // bias 1 init
    {
        const float2* bb = (const float2*)b1_;
        float2 bv0 = bb[k * BS + ob + q];
        float2 bv1 = bb[k * BS + ob + q + 8];
        #pragma unroll
        for (int t = 0; t < 8; t++) {
            Or[t][0] = bv0.x; Or[t][1] = bv0.x; Or[t][2] = bv1.x; Or[t][3] = bv1.x;
            Oi[t][0] = bv0.y; Oi[t][1] = bv0.y; Oi[t][2] = bv1.y; Oi[t][3] = bv1.y;
        }
    }

    const float2* inb = in + (size_t)k * BS * S_;
    const float2* wb1 = (const float2*)w1_ + (size_t)k * BS * BS;
    const float2* wb2 = (const float2*)w2_ + (size_t)k * BS * BS;

    // ---- GEMM 1 ----
    for (int ic = 0; ic < BS; ic += 32) {
        for (int t = tid; t < 32 * 96; t += 192) {
            int i = t / 96, o = t % 96;
            float2 wv = wb1[(size_t)(ic + i) * BS + o];
            WSR[i * PW + o] = f2tf(wv.x);
            WSI[i * PW + o] = f2tf(wv.y);
        }
        for (int t = tid; t < 32 * 64; t += 192) {
            int i = t >> 6, sl = t & 63;
            int s = s0 + sl;
            float2 v = (s < S_) ? inb[(size_t)(ic + i) * S_ + s]
                                : make_float2(0.f, 0.f);
            ASR[i * PA + sl] = f2tf(v.x);
            ASI[i * PA + sl] = f2tf(v.y);
        }
        __syncthreads();
        #pragma unroll
        for (int k0 = 0; k0 < 32; k0 += 8) {
            uint32_t awr0 = WSR[(k0 + r) * PW + ob + q];
            uint32_t awr1 = WSR[(k0 + r) * PW + ob + q + 8];
            uint32_t awr2 = WSR[(k0 + r + 4) * PW + ob + q];
            uint32_t awr3 = WSR[(k0 + r + 4) * PW + ob + q + 8];
            uint32_t awi0 = WSI[(k0 + r) * PW + ob + q];
            uint32_t awi1 = WSI[(k0 + r) * PW + ob + q + 8];
            uint32_t awi2 = WSI[(k0 + r + 4) * PW + ob + q];
            uint32_t awi3 = WSI[(k0 + r + 4) * PW + ob + q + 8];
            uint32_t nwi0 = awi0 ^ 0x80000000u, nwi1 = awi1 ^ 0x80000000u;
            uint32_t nwi2 = awi2 ^ 0x80000000u, nwi3 = awi3 ^ 0x80000000u;
            #pragma unroll
            for (int t = 0; t < 8; t++) {
                uint32_t br0 = ASR[(k0 + r) * PA + 8 * t + q];
                uint32_t br1 = ASR[(k0 + r + 4) * PA + 8 * t + q];
                uint32_t bi0 = ASI[(k0 + r) * PA + 8 * t + q];
                uint32_t bi1 = ASI[(k0 + r + 4) * PA + 8 * t + q];
                mma_tf32(Or[t], awr0, awr1, awr2, awr3, br0, br1);
                mma_tf32(Or[t], nwi0, nwi1, nwi2, nwi3, bi0, bi1);
                mma_tf32(Oi[t], awr0, awr1, awr2, awr3, bi0, bi1);
                mma_tf32(Oi[t], awi0, awi1, awi2, awi3, br0, br1);
            }
        }
        __syncthreads();
    }

    // relu -> o1 (tf32 in smem, [o][s])
    #pragma unroll
    for (int t = 0; t < 8; t++) {
        int sa = 8 * t + 2 * r;
        O1R[(ob + q    ) * PA + sa    ] = f2tf(fmaxf(Or[t][0], 0.f));
        O1R[(ob + q    ) * PA + sa + 1] = f2tf(fmaxf(Or[t][1], 0.f));
        O1R[(ob + q + 8) * PA + sa    ] = f2tf(fmaxf(Or[t][2], 0.f));
        O1R[(ob + q + 8) * PA + sa + 1] = f2tf(fmaxf(Or[t][3], 0.f));
        O1I[(ob + q    ) * PA + sa    ] = f2tf(fmaxf(Oi[t][0], 0.f));
        O1I[(ob + q    ) * PA + sa + 1] = f2tf(fmaxf(Oi[t][1], 0.f));
        O1I[(ob + q + 8) * PA + sa    ] = f2tf(fmaxf(Oi[t][2], 0.f));
        O1I[(ob + q + 8) * PA + sa + 1] = f2tf(fmaxf(Oi[t][3], 0.f));
    }
    // bias 2 init
    {
        const float2* bb = (const float2*)b2_;
        float2 bv0 = bb[k * BS + ob + q];
        float2 bv1 = bb[k * BS + ob + q + 8];
        #pragma unroll
        for (int t = 0; t < 8; t++) {
            Or[t][0] = bv0.x; Or[t][1] = bv0.x; Or[t][2] = bv1.x; Or[t][3] = bv1.x;
            Oi[t][0] = bv0.y; Oi[t][1] = bv0.y; Oi[t][2] = bv1.y; Oi[t][3] = bv1.y;
        }
    }
    __syncthreads();

    // ---- GEMM 2 (B operand = o1 in smem) ----
    for (int ic = 0; ic < BS; ic += 32) {
        for (int t = tid; t < 32 * 96; t += 192) {
            int i = t / 96, o = t % 96;
            float2 wv = wb2[(size_t)(ic + i) * BS + o];
            WSR[i * PW + o] = f2tf(wv.x);
            WSI[i * PW + o] = f2tf(wv.y);
        }
        __syncthreads();
        #pragma unroll
        for (int k0 = 0; k0 < 32; k0 += 8) {
            uint32_t awr0 = WSR[(k0 + r) * PW + ob + q];
            uint32_t awr1 = WSR[(k0 + r) * PW + ob + q + 8];
            uint32_t awr2 = WSR[(k0 + r + 4) * PW + ob + q];
            uint32_t awr3 = WSR[(k0 + r + 4) * PW + ob + q + 8];
            uint32_t awi0 = WSI[(k0 + r) * PW + ob + q];
            uint32_t awi1 = WSI[(k0 + r) * PW + ob + q + 8];
            uint32_t awi2 = WSI[(k0 + r + 4) * PW + ob + q];
            uint32_t awi3 = WSI[(k0 + r + 4) * PW + ob + q + 8];
            uint32_t nwi0 = awi0 ^ 0x80000000u, nwi1 = awi1 ^ 0x80000000u;
            uint32_t nwi2 = awi2 ^ 0x80000000u, nwi3 = awi3 ^ 0x80000000u;
            int kb = ic + k0;
            #pragma unroll
            for (int t = 0; t < 8; t++) {
                uint32_t br0 = O1R[(kb + r) * PA + 8 * t + q];
                uint32_t br1 = O1R[(kb + r + 4) * PA + 8 * t + q];
                uint32_t bi0 = O1I[(kb + r) * PA + 8 * t + q];
                uint32_t bi1 = O1I[(kb + r + 4) * PA + 8 * t + q];
                mma_tf32(Or[t], awr0, awr1, awr2, awr3, br0, br1);
                mma_tf32(Or[t], nwi0, nwi1, nwi2, nwi3, bi0, bi1);
                mma_tf32(Oi[t], awr0, awr1, awr2, awr3, bi0, bi1);
                mma_tf32(Oi[t], awi0, awi1, awi2, awi3, br0, br1);
            }
        }
        __syncthreads();
    }

    // softshrink epilogue -> global [o][s]
    #pragma unroll
    for (int t = 0; t < 8; t++) {
        int sa = 8 * t + 2 * r;
        #pragma unroll
        for (int c = 0; c < 4; c++) {
            int o = ob + q + ((c >= 2) ? 8 : 0);
            int s = s0 + sa + (c & 1);
            if (s < S_) {
                float rr = Or[t][c], mm = Oi[t][c];
                rr = copysignf(fmaxf(fabsf(rr) - LAM, 0.f), rr);
                mm = copysignf(fmaxf(fabsf(mm) - LAM, 0.f), mm);
                out[(size_t)k * BS * S_ + (size_t)o * S_ + s] = make_float2(rr, mm);
            }
        }
    }
}

// ---------------------------------------------------------------------------
// Kernel 6: inverse c2r W DFT, parity-split partial sums.
// (unchanged from R12 passing version)
// ---------------------------------------------------------------------------
__global__ __launch_bounds__(192)
void k_inv_w(const float* __restrict__ x, float* __restrict__ out) {
    __shared__ float2 tws[16 * 96];                    // [i][n]
    __shared__ __align__(16) float2 xs[16 * 34];       // [i][row], pad 34
    int r0  = blockIdx.x * 32;
    int x_  = threadIdx.x;           // 0..47
    int y_  = threadIdx.y;           // 0..3
    int tid = x_ + 48 * y_;
    int jb  = y_ * 8;

    float Ue[2][8], Uo[2][8], Ve[2][8], Vo[2][8];
    #pragma unroll
    for (int b = 0; b < 2; b++)
        #pragma unroll
        for (int j = 0; j < 8; j++) {
            Ue[b][j] = 0.f; Uo[b][j] = 0.f; Ve[b][j] = 0.f; Vo[b][j] = 0.f;
        }

    for (int w0 = 0; w0 < 96; w0 += 16) {
        for (int tt = tid; tt < 16 * 96; tt += 192)
            tws[tt] = g_Ti[w0 * 96 + tt];
        for (int tt = tid; tt < 16 * 32; tt += 192) {
            int i = tt & 15, j = tt >> 4;
            int w = w0 + i;
            float2 v = (w < WK) ? g_S2[(size_t)(r0 + j) * WK + w]
                                : make_float2(0.f, 0.f);
            xs[i * 34 + j] = v;
        }
        __syncthreads();
        #pragma unroll
        for (int i2 = 0; i2 < 8; i2++) {
            {   // even w
                int i = 2 * i2;
                float2 wv0 = tws[i * 96 + x_];
                float2 wv1 = tws[i * 96 + x_ + 48];
                const float4* ap = reinterpret_cast<const float4*>(&xs[i * 34 + jb]);
                #pragma unroll
                for (int jp = 0; jp < 4; jp++) {
                    float4 v = ap[jp];
                    Ue[0][2*jp  ] = fmaf(v.x, wv0.x, Ue[0][2*jp  ]);
                    Ve[0][2*jp  ] = fmaf(v.y, wv0.y, Ve[0][2*jp  ]);
                    Ue[0][2*jp+1] = fmaf(v.z, wv0.x, Ue[0][2*jp+1]);
                    Ve[0][2*jp+1] = fmaf(v.w, wv0.y, Ve[0][2*jp+1]);
                    Ue[1][2*jp  ] = fmaf(v.x, wv1.x, Ue[1][2*jp  ]);
                    Ve[1][2*jp  ] = fmaf(v.y, wv1.y, Ve[1][2*jp  ]);
                    Ue[1][2*jp+1] = fmaf(v.z, wv1.x, Ue[1][2*jp+1]);
                    Ve[1][2*jp+1] = fmaf(v.w, wv1.y, Ve[1][2*jp+1]);
                }
            }
            {   // odd w
                int i = 2 * i2 + 1;
                float2 wv0 = tws[i * 96 + x_];
                float2 wv1 = tws[i * 96 + x_ + 48];
                const float4* ap = reinterpret_cast<const float4*>(&xs[i * 34 + jb]);
                #pragma unroll
                for (int jp = 0; jp < 4; jp++) {
                    float4 v = ap[jp];
                    Uo[0][2*jp  ] = fmaf(v.x, wv0.x, Uo[0][2*jp  ]);
                    Vo[0][2*jp  ] = fmaf(v.y, wv0.y, Vo[0][2*jp  ]);
                    Uo[0][2*jp+1] = fmaf(v.z, wv0.x, Uo[0][2*jp+1]);
                    Vo[0][2*jp+1] = fmaf(v.w, wv0.y, Vo[0][2*jp+1]);
                    Uo[1][2*jp  ] = fmaf(v.x, wv1.x, Uo[1][2*jp  ]);
                    Vo[1][2*jp  ] = fmaf(v.y, wv1.y, Vo[1][2*jp  ]);
                    Uo[1][2*jp+1] = fmaf(v.z, wv1.x, Uo[1][2*jp+1]);
                    Vo[1][2*jp+1] = fmaf(v.w, wv1.y, Vo[1][2*jp+1]);
                }
            }
        }
        __syncthreads();
    }

    const float k2 = 2.0f * ORTHO;
    #pragma unroll
    for (int b = 0; b < 2; b++) {
        int n = x_ + 48 * b;
        if (n <= 90) {
            #pragma unroll
            for (int j = 0; j < 8; j++) {
                size_t rb = (size_t)(r0 + jb + j) * W_;
                float ue = Ue[b][j], uo = Uo[b][j];
                float ve = Ve[b][j], vo = Vo[b][j];
                out[rb + n] = fmaf(k2, ue + uo - ve - vo, x[rb + n]);
                if (n >= 1)
                    out[rb + W_ - n] = fmaf(k2, ue + uo + ve + vo, x[rb + W_ - n]);
                if (n >= 1 && n <= 89) {
                    out[rb + 180 - n] = fmaf(k2, ue - uo + ve - vo, x[rb + 180 - n]);
                    out[rb + 180 + n] = fmaf(k2, ue - uo - ve + vo, x[rb + 180 + n]);
                }
                if (n == 0)
                    out[rb + 180] = fmaf(k2, ue - uo, x[rb + 180]);
            }
        }
    }
}

// ---------------------------------------------------------------------------
extern "C" void kernel_launch(void* const* d_in, const int* in_sizes, int n_in,
                              void* d_out, int out_size) {
    const float* x  = (const float*)d_in[0];
    const float* w1 = (const float*)d_in[1];
    const float* b1 = (const float*)d_in[2];
    const float* w2 = (const float*)d_in[3];
    const float* b2 = (const float*)d_in[4];
    float* out = (float*)d_out;

    float2* S1; float2* S2;
    cudaGetSymbolAddress((void**)&S1, g_S1);
    cudaGetSymbolAddress((void**)&S2, g_S2);

    const int stiles   = (S_ + 63) / 64;           // 256
    const int mix_smem = MIX_SMEM_WORDS * 4;       // ~100 KB
    const int fwd_smem = (32 * 96 + 2 * 32 * 66) * (int)sizeof(float2);

    cudaFuncSetAttribute(k_mix_f,
                         cudaFuncAttributeMaxDynamicSharedMemorySize, mix_smem);
    cudaFuncSetAttribute(k_fwd_w,
                         cudaFuncAttributeMaxDynamicSharedMemorySize, fwd_smem);

    // 0. DFT matrices + twiddles
    k_init_T<<<(96 * 96 + 255) / 256, 256>>>();
    // 1. forward W DFT (fold fused; x -> S1), ortho-scaled
    k_fwd_w<<<ROWS / 64, dim3(48, 4), fwd_smem>>>(x);
    // 2. forward H DFT (S1 -> S2)
    k_fft_h<-1><<<dim3(WK / WT, CH), 224>>>(S1, S2);
    // 3+4. fused tensor-core mix: relu(w1) then softshrink(w2)  (S2 -> S1)
    k_mix_f<<<dim3(stiles, NB), 192, mix_smem>>>(S2, S1, w1, b1, w2, b2);
    // 5. inverse H DFT (S1 -> S2)
    k_fft_h<+1><<<dim3(WK / WT, CH), 224>>>(S1, S2);
    // 6. inverse W c2r (parity-split) + residual (S2, x -> out)
    k_inv_w<<<ROWS / 32, dim3(48, 4)>>>(x, out);
}